// round 3
// baseline (speedup 1.0000x reference)
#include <cuda_runtime.h>
#include <cuda_bf16.h>
#include <math.h>

#define NEG 0.01f

// ---------------------------------------------------------------------------
// Scratch (allocation-free rule: __device__ globals)
// ---------------------------------------------------------------------------
__device__ __align__(16) float g_K[4 * 64 * 64];      // 4 normalized gaussian kernels
__device__ int g_band[4];                             // band radius per layer
__device__ __align__(16) __nv_bfloat16 g_wHi[80 * 4096];   // wm0 split hi [o][k]
__device__ __align__(16) __nv_bfloat16 g_wLo[80 * 4096];   // wm0 split lo
__device__ __align__(16) __nv_bfloat16 g_hHi[(size_t)16384 * 4096]; // H split hi [b][k]
__device__ __align__(16) __nv_bfloat16 g_hLo[(size_t)16384 * 4096]; // H split lo

// ---------------------------------------------------------------------------
// Kernel K: build 4 L1-normalized gaussian mixing matrices + band radii
// ---------------------------------------------------------------------------
__global__ void kernK(const float* __restrict__ s0, const float* __restrict__ s1,
                      const float* __restrict__ s2, const float* __restrict__ s3) {
    int t = threadIdx.x;              // 256 threads = 4 layers * 64 rows
    int l = t >> 6, i = t & 63;
    float sg = (l == 0) ? s0[0] : (l == 1) ? s1[0] : (l == 2) ? s2[0] : s3[0];
    float denom = 2.0f * sg * sg;
    float sum = 0.0f;
    for (int j = 0; j < 64; j++) {
        float d = (float)(i - j);
        sum += expf(-(d * d) / denom);
    }
    sum = fmaxf(sum, 1e-12f);
    for (int j = 0; j < 64; j++) {
        float d = (float)(i - j);
        g_K[(l * 64 + i) * 64 + j] = expf(-(d * d) / denom) / sum;
    }
    if (i == 0) {
        // radius where unnormalized weight drops below 1e-8 (normalized <= 1e-8
        // since row-sum >= 1). Cap 63 => exact full-width fallback.
        float rr = sqrtf(fmaxf(denom, 0.0f) * 18.5f);
        int R = (int)rr + 1;
        if (R > 63) R = 63;
        g_band[l] = R;
    }
}

// ---------------------------------------------------------------------------
// Kernel T: split wm0 [80][4096] fp32 -> bf16 hi/lo (same layout)
// ---------------------------------------------------------------------------
__global__ void kernT(const float* __restrict__ wm0) {
    int idx = blockIdx.x * blockDim.x + threadIdx.x;
    if (idx >= 80 * 4096) return;
    float v = wm0[idx];
    __nv_bfloat16 hi = __float2bfloat16_rn(v);
    __nv_bfloat16 lo = __float2bfloat16_rn(v - __bfloat162float(hi));
    g_wHi[idx] = hi;
    g_wLo[idx] = lo;
}

// ---------------------------------------------------------------------------
// Kernel G: fused 4-layer gaussian stack.
// 1 block = 16 samples processed as TWO independent streams of 8 samples
// (512 threads: sub = tid>>8 picks the stream, t = tid&255 is the worker id).
// Reordered algebra: since rows of K sum to 1, K@(xW+b) = (K@x)W + b; layer 0
// keeps original order (shrink channels first). Mixes use banded K.
// Shared (floats): sK 4*64*65 @0 | W0t@16640 W1t@17152 W2t@17280 W3t@17792 |
// B0..B3 @19840.. | per-stream bufA/bufB (64x68) @19960 (+8704 per stream).
// Total 37368 floats = 149472 B dynamic.
// ---------------------------------------------------------------------------
__global__ __launch_bounds__(512) void kernG(
    const float* __restrict__ x,
    const float* __restrict__ w0, const float* __restrict__ b0,
    const float* __restrict__ w1, const float* __restrict__ b1,
    const float* __restrict__ w2, const float* __restrict__ b2,
    const float* __restrict__ w3, const float* __restrict__ b3)
{
    extern __shared__ __align__(16) float sm[];
    float* sK  = sm;
    float* sW0 = sm + 16640;
    float* sW1 = sm + 17152;
    float* sW2 = sm + 17280;
    float* sW3 = sm + 17792;
    float* sB0 = sm + 19840;
    float* sB1 = sm + 19848;
    float* sB2 = sm + 19864;
    float* sB3 = sm + 19896;

    const int tid = threadIdx.x;
    const int sub = tid >> 8;
    const int t   = tid & 255;
    float* bufA = sm + 19960 + sub * 8704;
    float* bufB = bufA + 4352;

    const int R0 = g_band[0], R1 = g_band[1], R2 = g_band[2], R3 = g_band[3];

    // stage kernels (stride 65) + transposed weights + biases (512 threads)
    for (int idx = tid; idx < 4 * 64 * 64; idx += 512) {
        int l = idx >> 12, rem = idx & 4095;
        int i = rem >> 6, j = rem & 63;
        sK[l * 4160 + i * 65 + j] = g_K[idx];
    }
    for (int idx = tid; idx < 8 * 64;  idx += 512) { int o = idx >> 6, c = idx & 63; sW0[c * 8  + o] = w0[idx]; }
    for (int idx = tid; idx < 16 * 8;  idx += 512) { int o = idx >> 3, c = idx & 7;  sW1[c * 16 + o] = w1[idx]; }
    for (int idx = tid; idx < 32 * 16; idx += 512) { int o = idx >> 4, c = idx & 15; sW2[c * 32 + o] = w2[idx]; }
    for (int idx = tid; idx < 64 * 32; idx += 512) { int o = idx >> 5, c = idx & 31; sW3[c * 64 + o] = w3[idx]; }
    if (tid < 8)  sB0[tid] = b0[tid];
    else if (tid >= 32 && tid < 48) sB1[tid - 32] = b1[tid - 32];
    else if (tid >= 64 && tid < 96) sB2[tid - 64] = b2[tid - 64];
    else if (tid >= 128 && tid < 192) sB3[tid - 128] = b3[tid - 128];
    __syncthreads();

    for (int s = 0; s < 8; s++) {
        const size_t b = (size_t)blockIdx.x * 16 + sub * 8 + s;

        // load x[b] (64x64) into bufA
        {
            const float4* xb = (const float4*)(x + b * 4096);
            for (int idx = t; idx < 1024; idx += 256) {
                int r = idx >> 4, c4 = idx & 15;
                *(float4*)(bufA + r * 68 + c4 * 4) = xb[idx];
            }
        }
        __syncthreads();

        // ---- L0 wmult: bufB[j][0..7] = bufA[j][:] @ W0t + b0 (no act yet)
        {
            int j = t >> 2, o0 = (t & 3) * 2;
            float a0 = sB0[o0], a1 = sB0[o0 + 1];
            const float* Ar = bufA + j * 68;
            #pragma unroll 8
            for (int c = 0; c < 64; c++) {
                float xv = Ar[c];
                a0 = fmaf(xv, sW0[c * 8 + o0], a0);
                a1 = fmaf(xv, sW0[c * 8 + o0 + 1], a1);
            }
            bufB[j * 68 + o0] = a0; bufB[j * 68 + o0 + 1] = a1;
        }
        __syncthreads();

        // ---- L0 mix + leaky: bufA = leaky(K0 @ bufB)   (C=8, banded)
        {
            int i = t >> 2, o0 = (t & 3) * 2;
            const float* Ki = sK + i * 65;
            int jlo = i - R0; if (jlo < 0) jlo = 0;
            int jhi = i + R0; if (jhi > 63) jhi = 63;
            float a0 = 0.f, a1 = 0.f;
            #pragma unroll 4
            for (int j = jlo; j <= jhi; j++) {
                float kv = Ki[j];
                float2 tv = *(const float2*)(bufB + j * 68 + o0);
                a0 = fmaf(kv, tv.x, a0);
                a1 = fmaf(kv, tv.y, a1);
            }
            a0 = a0 > 0.f ? a0 : a0 * NEG;
            a1 = a1 > 0.f ? a1 : a1 * NEG;
            bufA[i * 68 + o0] = a0; bufA[i * 68 + o0 + 1] = a1;
        }
        __syncthreads();

        // ---- L1 mix: bufB = K1 @ bufA   (C=8, banded, no act)
        {
            int i = t >> 2, o0 = (t & 3) * 2;
            const float* Ki = sK + 4160 + i * 65;
            int jlo = i - R1; if (jlo < 0) jlo = 0;
            int jhi = i + R1; if (jhi > 63) jhi = 63;
            float a0 = 0.f, a1 = 0.f;
            #pragma unroll 4
            for (int j = jlo; j <= jhi; j++) {
                float kv = Ki[j];
                float2 tv = *(const float2*)(bufA + j * 68 + o0);
                a0 = fmaf(kv, tv.x, a0);
                a1 = fmaf(kv, tv.y, a1);
            }
            bufB[i * 68 + o0] = a0; bufB[i * 68 + o0 + 1] = a1;
        }
        __syncthreads();

        // ---- L1 wmult + leaky: bufA[j][0..15] = leaky(bufB[j][:8] @ W1t + b1)
        {
            int j0 = (t >> 3) * 2, o0 = (t & 7) * 2;
            float a00 = sB1[o0], a01 = sB1[o0 + 1];
            float a10 = a00, a11 = a01;
            #pragma unroll
            for (int c = 0; c < 8; c++) {
                float i0 = bufB[j0 * 68 + c], i1 = bufB[(j0 + 1) * 68 + c];
                float wv0 = sW1[c * 16 + o0], wv1 = sW1[c * 16 + o0 + 1];
                a00 = fmaf(i0, wv0, a00); a01 = fmaf(i0, wv1, a01);
                a10 = fmaf(i1, wv0, a10); a11 = fmaf(i1, wv1, a11);
            }
            a00 = a00 > 0.f ? a00 : a00 * NEG; a01 = a01 > 0.f ? a01 : a01 * NEG;
            a10 = a10 > 0.f ? a10 : a10 * NEG; a11 = a11 > 0.f ? a11 : a11 * NEG;
            bufA[j0 * 68 + o0] = a00;       bufA[j0 * 68 + o0 + 1] = a01;
            bufA[(j0 + 1) * 68 + o0] = a10; bufA[(j0 + 1) * 68 + o0 + 1] = a11;
        }
        __syncthreads();

        // ---- L2 mix: bufB = K2 @ bufA  (C=16, banded), 2i x 2o
        {
            int i0 = (t >> 3) * 2, o0 = (t & 7) * 2;
            const float* K0r = sK + 2 * 4160 + i0 * 65;
            const float* K1r = K0r + 65;
            int jlo = i0 - R2; if (jlo < 0) jlo = 0;
            int jhi = i0 + 1 + R2; if (jhi > 63) jhi = 63;
            float a00 = 0.f, a01 = 0.f, a10 = 0.f, a11 = 0.f;
            #pragma unroll 4
            for (int j = jlo; j <= jhi; j++) {
                float2 tv = *(const float2*)(bufA + j * 68 + o0);
                float k0 = K0r[j], k1 = K1r[j];
                a00 = fmaf(k0, tv.x, a00); a01 = fmaf(k0, tv.y, a01);
                a10 = fmaf(k1, tv.x, a10); a11 = fmaf(k1, tv.y, a11);
            }
            bufB[i0 * 68 + o0] = a00;       bufB[i0 * 68 + o0 + 1] = a01;
            bufB[(i0 + 1) * 68 + o0] = a10; bufB[(i0 + 1) * 68 + o0 + 1] = a11;
        }
        __syncthreads();

        // ---- L2 wmult + leaky: bufA[j][0..31] = leaky(bufB[j][:16] @ W2t + b2)
        {
            int j0 = (t >> 4) * 4, o0 = (t & 15) * 2;
            float acc[4][2];
            #pragma unroll
            for (int jj = 0; jj < 4; jj++) { acc[jj][0] = sB2[o0]; acc[jj][1] = sB2[o0 + 1]; }
            #pragma unroll
            for (int c = 0; c < 16; c++) {
                float wv0 = sW2[c * 32 + o0], wv1 = sW2[c * 32 + o0 + 1];
                #pragma unroll
                for (int jj = 0; jj < 4; jj++) {
                    float iv = bufB[(j0 + jj) * 68 + c];
                    acc[jj][0] = fmaf(iv, wv0, acc[jj][0]);
                    acc[jj][1] = fmaf(iv, wv1, acc[jj][1]);
                }
            }
            #pragma unroll
            for (int jj = 0; jj < 4; jj++) {
                float v0 = acc[jj][0], v1 = acc[jj][1];
                v0 = v0 > 0.f ? v0 : v0 * NEG;
                v1 = v1 > 0.f ? v1 : v1 * NEG;
                bufA[(j0 + jj) * 68 + o0] = v0;
                bufA[(j0 + jj) * 68 + o0 + 1] = v1;
            }
        }
        __syncthreads();

        // ---- L3 mix: bufB = K3 @ bufA  (C=32, banded), 4i x 2o
        {
            int i0 = (t >> 4) * 4, o0 = (t & 15) * 2;
            const float* Kb = sK + 3 * 4160;
            int jlo = i0 - R3; if (jlo < 0) jlo = 0;
            int jhi = i0 + 3 + R3; if (jhi > 63) jhi = 63;
            float acc[4][2] = {{0.f,0.f},{0.f,0.f},{0.f,0.f},{0.f,0.f}};
            #pragma unroll 4
            for (int j = jlo; j <= jhi; j++) {
                float2 tv = *(const float2*)(bufA + j * 68 + o0);
                #pragma unroll
                for (int ii = 0; ii < 4; ii++) {
                    float kv = Kb[(i0 + ii) * 65 + j];
                    acc[ii][0] = fmaf(kv, tv.x, acc[ii][0]);
                    acc[ii][1] = fmaf(kv, tv.y, acc[ii][1]);
                }
            }
            #pragma unroll
            for (int ii = 0; ii < 4; ii++) {
                bufB[(i0 + ii) * 68 + o0] = acc[ii][0];
                bufB[(i0 + ii) * 68 + o0 + 1] = acc[ii][1];
            }
        }
        __syncthreads();

        // ---- L3 wmult + leaky: bufA[j][0..63] = leaky(bufB[j][:32] @ W3t + b3)
        {
            int j0 = (t >> 4) * 4, o0 = (t & 15) * 4;
            float acc[4][4];
            #pragma unroll
            for (int jj = 0; jj < 4; jj++)
                #pragma unroll
                for (int oo = 0; oo < 4; oo++)
                    acc[jj][oo] = sB3[o0 + oo];
            #pragma unroll
            for (int c = 0; c < 32; c++) {
                float4 wv = *(const float4*)(sW3 + c * 64 + o0);
                #pragma unroll
                for (int jj = 0; jj < 4; jj++) {
                    float iv = bufB[(j0 + jj) * 68 + c];
                    acc[jj][0] = fmaf(iv, wv.x, acc[jj][0]);
                    acc[jj][1] = fmaf(iv, wv.y, acc[jj][1]);
                    acc[jj][2] = fmaf(iv, wv.z, acc[jj][2]);
                    acc[jj][3] = fmaf(iv, wv.w, acc[jj][3]);
                }
            }
            #pragma unroll
            for (int jj = 0; jj < 4; jj++) {
                float4 v;
                v.x = acc[jj][0] > 0.f ? acc[jj][0] : acc[jj][0] * NEG;
                v.y = acc[jj][1] > 0.f ? acc[jj][1] : acc[jj][1] * NEG;
                v.z = acc[jj][2] > 0.f ? acc[jj][2] : acc[jj][2] * NEG;
                v.w = acc[jj][3] > 0.f ? acc[jj][3] : acc[jj][3] * NEG;
                *(float4*)(bufA + (j0 + jj) * 68 + o0) = v;
            }
        }
        __syncthreads();

        // write to scratch as split bf16 hi/lo [b][4096]
        {
            for (int idx = t; idx < 2048; idx += 256) {
                int r = idx >> 5, c2 = idx & 31;
                float2 v = *(const float2*)(bufA + r * 68 + c2 * 2);
                __nv_bfloat16 h0 = __float2bfloat16_rn(v.x);
                __nv_bfloat16 h1 = __float2bfloat16_rn(v.y);
                __nv_bfloat16 l0 = __float2bfloat16_rn(v.x - __bfloat162float(h0));
                __nv_bfloat16 l1 = __float2bfloat16_rn(v.y - __bfloat162float(h1));
                __nv_bfloat162 ph; ph.x = h0; ph.y = h1;
                __nv_bfloat162 pl; pl.x = l0; pl.y = l1;
                *(__nv_bfloat162*)(g_hHi + b * 4096 + r * 64 + c2 * 2) = ph;
                *(__nv_bfloat162*)(g_hLo + b * 4096 + r * 64 + c2 * 2) = pl;
            }
        }
        __syncthreads();
    }
}

// ---------------------------------------------------------------------------
// Kernel C: tensor-core compress MLP.
// Layer1: out1 = leaky(H @ wm0T + bm0), split-bf16 (Ah*Bh + Ah*Bl + Al*Bh)
// via mma.sync.m16n8k16, fp32 accum -> ~1e-5 rel error.
// Block: 128 rows x 80 cols, K-chunks of 64, cp.async double-buffered.
// 8 warps: (wm 0..3) x (wn 0..1); warp tile 32x40 (2 m16 x 5 n8).
// Layer2: out = leaky(out1 @ wm1T + bm1) in fp32 SIMT (tiny).
// ---------------------------------------------------------------------------
#define KC_STAGE_H   29952               // halves per stage
#define KC_SA_H      0                   // sA hi offset (halves)
#define KC_SA_L      9216
#define KC_SW_H      18432
#define KC_SW_L      24192
#define KC_F32_OFF   119808              // bytes: start of persistent fp32 region
#define KC_SMEM_BYTES (119808 + 21056)

__device__ __forceinline__ void kc_ldmatrix_x4(unsigned& r0, unsigned& r1,
                                               unsigned& r2, unsigned& r3,
                                               const __nv_bfloat16* p) {
    unsigned addr = (unsigned)__cvta_generic_to_shared(p);
    asm volatile("ldmatrix.sync.aligned.m8n8.x4.shared.b16 {%0,%1,%2,%3}, [%4];"
                 : "=r"(r0), "=r"(r1), "=r"(r2), "=r"(r3) : "r"(addr));
}
__device__ __forceinline__ void kc_ldmatrix_x2(unsigned& r0, unsigned& r1,
                                               const __nv_bfloat16* p) {
    unsigned addr = (unsigned)__cvta_generic_to_shared(p);
    asm volatile("ldmatrix.sync.aligned.m8n8.x2.shared.b16 {%0,%1}, [%2];"
                 : "=r"(r0), "=r"(r1) : "r"(addr));
}
__device__ __forceinline__ void kc_mma(float* c, unsigned a0, unsigned a1,
                                       unsigned a2, unsigned a3,
                                       unsigned b0, unsigned b1) {
    asm volatile("mma.sync.aligned.m16n8k16.row.col.f32.bf16.bf16.f32 "
                 "{%0,%1,%2,%3}, {%4,%5,%6,%7}, {%8,%9}, {%0,%1,%2,%3};"
                 : "+f"(c[0]), "+f"(c[1]), "+f"(c[2]), "+f"(c[3])
                 : "r"(a0), "r"(a1), "r"(a2), "r"(a3), "r"(b0), "r"(b1));
}
__device__ __forceinline__ void kc_cpasync16(__nv_bfloat16* dst, const __nv_bfloat16* src) {
    unsigned d = (unsigned)__cvta_generic_to_shared(dst);
    asm volatile("cp.async.cg.shared.global [%0], [%1], 16;" :: "r"(d), "l"(src));
}

__global__ __launch_bounds__(256) void kernC(const float* __restrict__ bm0,
                                             const float* __restrict__ wm1,
                                             const float* __restrict__ bm1,
                                             float* __restrict__ out)
{
    extern __shared__ __align__(16) char smc[];
    __nv_bfloat16* sh = (__nv_bfloat16*)smc;
    float* fpers = (float*)(smc + KC_F32_OFF);
    float* sWm1t = fpers;            // [80][64] (pad 64)
    float* sBm0  = fpers + 5120;     // 80
    float* sBm1  = fpers + 5200;     // 60
    float* sOut1 = (float*)smc;      // [128][84] reuses tile region after k-loop

    const int tid  = threadIdx.x;
    const int lane = tid & 31;
    const int warp = tid >> 5;
    const int wm = warp >> 1, wn = warp & 1;
    const int m0 = blockIdx.x * 128;

    // persistent staging: wm1 transposed + biases
    for (int idx = tid; idx < 4800; idx += 256) {
        int o = idx / 80, c = idx % 80;
        sWm1t[c * 64 + o] = wm1[idx];
    }
    if (tid < 80) sBm0[tid] = bm0[tid];
    if (tid < 60) sBm1[tid] = bm1[tid];

    // cp.async stage loader
    auto load_stage = [&](int kb, int st) {
        __nv_bfloat16* base = sh + st * KC_STAGE_H;
        const size_t kcol = (size_t)kb * 64;
        #pragma unroll
        for (int c = tid; c < 1024; c += 256) {
            int r = c >> 3, o = c & 7;
            kc_cpasync16(base + KC_SA_H + r * 72 + o * 8,
                         g_hHi + (size_t)(m0 + r) * 4096 + kcol + o * 8);
        }
        #pragma unroll
        for (int c = tid; c < 1024; c += 256) {
            int r = c >> 3, o = c & 7;
            kc_cpasync16(base + KC_SA_L + r * 72 + o * 8,
                         g_hLo + (size_t)(m0 + r) * 4096 + kcol + o * 8);
        }
        for (int c = tid; c < 640; c += 256) {
            int r = c >> 3, o = c & 7;
            kc_cpasync16(base + KC_SW_H + r * 72 + o * 8,
                         g_wHi + (size_t)r * 4096 + kcol + o * 8);
        }
        for (int c = tid; c < 640; c += 256) {
            int r = c >> 3, o = c & 7;
            kc_cpasync16(base + KC_SW_L + r * 72 + o * 8,
                         g_wLo + (size_t)r * 4096 + kcol + o * 8);
        }
    };

    float acc[2][5][4];
    #pragma unroll
    for (int i = 0; i < 2; i++)
        #pragma unroll
        for (int j = 0; j < 5; j++)
            #pragma unroll
            for (int k = 0; k < 4; k++) acc[i][j][k] = 0.f;

    load_stage(0, 0);
    asm volatile("cp.async.commit_group;");

    // precomputed lane offsets
    const int aq  = lane >> 3;          // 0..3 matrix id
    const int arn = lane & 7;
    const int a_row_off = (aq & 1) * 8 + arn;   // within m16
    const int a_col_off = (aq >> 1) * 8;        // within k16
    const int bl  = lane & 15;
    const int b_rn = bl & 7;
    const int b_hi8 = (bl >> 3) * 8;

    const int NK = 64;
    for (int kb = 0; kb < NK; kb++) {
        if (kb + 1 < NK) {
            load_stage(kb + 1, (kb + 1) & 1);
            asm volatile("cp.async.commit_group;");
            asm volatile("cp.async.wait_group 1;");
        } else {
            asm volatile("cp.async.wait_group 0;");
        }
        __syncthreads();

        __nv_bfloat16* base = sh + (kb & 1) * KC_STAGE_H;
        __nv_bfloat16* sAh = base + KC_SA_H;
        __nv_bfloat16* sAl = base + KC_SA_L;
        __nv_bfloat16* sWh = base + KC_SW_H;
        __nv_bfloat16* sWl = base + KC_SW_L;

        #pragma unroll
        for (int sub = 0; sub < 4; sub++) {
            const int kc = sub * 16;
            // B fragments: 5 ntiles x {hi, lo}
            unsigned bh[5][2], blo[5][2];
            #pragma unroll
            for (int n = 0; n < 5; n++) {
                const int brow = wn * 40 + n * 8 + b_rn;
                kc_ldmatrix_x2(bh[n][0],  bh[n][1],  sWh + brow * 72 + kc + b_hi8);
                kc_ldmatrix_x2(blo[n][0], blo[n][1], sWl + brow * 72 + kc + b_hi8);
            }
            #pragma unroll
            for (int tmt = 0; tmt < 2; tmt++) {
                const int arow = wm * 32 + tmt * 16 + a_row_off;
                unsigned ah0, ah1, ah2, ah3, al0, al1, al2, al3;
                kc_ldmatrix_x4(ah0, ah1, ah2, ah3, sAh + arow * 72 + kc + a_col_off);
                kc_ldmatrix_x4(al0, al1, al2, al3, sAl + arow * 72 + kc + a_col_off);
                #pragma unroll
                for (int n = 0; n < 5; n++) {
                    kc_mma(acc[tmt][n], ah0, ah1, ah2, ah3, bh[n][0],  bh[n][1]);
                    kc_mma(acc[tmt][n], ah0, ah1, ah2, ah3, blo[n][0], blo[n][1]);
                    kc_mma(acc[tmt][n], al0, al1, al2, al3, bh[n][0],  bh[n][1]);
                }
            }
        }
        __syncthreads();
    }

    // epilogue layer 1: bias + leaky -> sOut1[128][84]
    #pragma unroll
    for (int tmt = 0; tmt < 2; tmt++)
        #pragma unroll
        for (int n = 0; n < 5; n++)
            #pragma unroll
            for (int cr = 0; cr < 4; cr++) {
                int row = wm * 32 + tmt * 16 + (lane >> 2) + ((cr >= 2) ? 8 : 0);
                int col = wn * 40 + n * 8 + (lane & 3) * 2 + (cr & 1);
                float v = acc[tmt][n][cr] + sBm0[col];
                v = v > 0.f ? v : v * NEG;
                sOut1[row * 84 + col] = v;
            }
    __syncthreads();

    // layer 2: out[128][60] = leaky(out1 @ wm1T + bm1)
    {
        const int tr = tid >> 4;       // 0..15, rows tr + 16*i
        const int tc = tid & 15;       // cols tc*4 .. tc*4+3 (guard >=60)
        float a2[8][4];
        #pragma unroll
        for (int i = 0; i < 8; i++)
            #pragma unroll
            for (int j = 0; j < 4; j++) a2[i][j] = 0.f;
        for (int c = 0; c < 80; c++) {
            float wv[4];
            #pragma unroll
            for (int j = 0; j < 4; j++) {
                int o = tc * 4 + j;
                wv[j] = (o < 60) ? sWm1t[c * 64 + o] : 0.f;
            }
            #pragma unroll
            for (int i = 0; i < 8; i++) {
                float cv = sOut1[(tr + 16 * i) * 84 + c];
                #pragma unroll
                for (int j = 0; j < 4; j++)
                    a2[i][j] = fmaf(cv, wv[j], a2[i][j]);
            }
        }
        #pragma unroll
        for (int i = 0; i < 8; i++)
            #pragma unroll
            for (int j = 0; j < 4; j++) {
                int o = tc * 4 + j;
                if (o < 60) {
                    float v = a2[i][j] + sBm1[o];
                    v = v > 0.f ? v : v * NEG;
                    out[(size_t)(m0 + tr + 16 * i) * 60 + o] = v;
                }
            }
    }
}

// ---------------------------------------------------------------------------
extern "C" void kernel_launch(void* const* d_in, const int* in_sizes, int n_in,
                              void* d_out, int out_size) {
    (void)in_sizes; (void)n_in; (void)out_size;
    const float* x   = (const float*)d_in[0];
    const float* w0  = (const float*)d_in[1];
    const float* b0  = (const float*)d_in[2];
    const float* s0  = (const float*)d_in[3];
    const float* w1  = (const float*)d_in[4];
    const float* b1  = (const float*)d_in[5];
    const float* s1  = (const float*)d_in[6];
    const float* w2  = (const float*)d_in[7];
    const float* b2  = (const float*)d_in[8];
    const float* s2  = (const float*)d_in[9];
    const float* w3  = (const float*)d_in[10];
    const float* b3  = (const float*)d_in[11];
    const float* s3  = (const float*)d_in[12];
    const float* wm0 = (const float*)d_in[13];
    const float* bm0 = (const float*)d_in[14];
    const float* wm1 = (const float*)d_in[15];
    const float* bm1 = (const float*)d_in[16];
    float* out = (float*)d_out;

    static int attr_done = 0;
    if (!attr_done) {
        cudaFuncSetAttribute(kernG, cudaFuncAttributeMaxDynamicSharedMemorySize, 149472);
        cudaFuncSetAttribute(kernC, cudaFuncAttributeMaxDynamicSharedMemorySize, KC_SMEM_BYTES);
        attr_done = 1;
    }

    kernK<<<1, 256>>>(s0, s1, s2, s3);
    kernT<<<1280, 256>>>(wm0);
    kernG<<<1024, 512, 149472>>>(x, w0, b0, w1, b1, w2, b2, w3, b3);
    kernC<<<128, 256, KC_SMEM_BYTES>>>(bm0, wm1, bm1, out);
}

// round 4
// speedup vs baseline: 1.0071x; 1.0071x over previous
#include <cuda_runtime.h>
#include <cuda_bf16.h>
#include <math.h>

#define NEG 0.01f

// ---------------------------------------------------------------------------
// Scratch (allocation-free rule: __device__ globals)
// ---------------------------------------------------------------------------
__device__ __align__(16) float g_K[4 * 64 * 64];      // 4 normalized gaussian kernels
__device__ int g_band[4];                             // band radius per layer
__device__ __align__(16) __nv_bfloat16 g_wHi[80 * 4096];   // wm0 split hi [o][k]
__device__ __align__(16) __nv_bfloat16 g_wLo[80 * 4096];   // wm0 split lo
__device__ __align__(16) __nv_bfloat16 g_hHi[(size_t)16384 * 4096]; // H split hi [b][k]
__device__ __align__(16) __nv_bfloat16 g_hLo[(size_t)16384 * 4096]; // H split lo

// ---------------------------------------------------------------------------
// Kernel K: build 4 L1-normalized gaussian mixing matrices + band radii
// ---------------------------------------------------------------------------
__global__ void kernK(const float* __restrict__ s0, const float* __restrict__ s1,
                      const float* __restrict__ s2, const float* __restrict__ s3) {
    int t = threadIdx.x;              // 256 threads = 4 layers * 64 rows
    int l = t >> 6, i = t & 63;
    float sg = (l == 0) ? s0[0] : (l == 1) ? s1[0] : (l == 2) ? s2[0] : s3[0];
    float denom = 2.0f * sg * sg;
    float sum = 0.0f;
    for (int j = 0; j < 64; j++) {
        float d = (float)(i - j);
        sum += expf(-(d * d) / denom);
    }
    sum = fmaxf(sum, 1e-12f);
    for (int j = 0; j < 64; j++) {
        float d = (float)(i - j);
        g_K[(l * 64 + i) * 64 + j] = expf(-(d * d) / denom) / sum;
    }
    if (i == 0) {
        // radius where unnormalized weight drops below 1e-8 (normalized <= 1e-8
        // since row-sum >= 1). Cap 63 => exact full-width fallback.
        float rr = sqrtf(fmaxf(denom, 0.0f) * 18.5f);
        int R = (int)rr + 1;
        if (R > 63) R = 63;
        g_band[l] = R;
    }
}

// ---------------------------------------------------------------------------
// Kernel T: split wm0 [80][4096] fp32 -> bf16 hi/lo (same layout)
// ---------------------------------------------------------------------------
__global__ void kernT(const float* __restrict__ wm0) {
    int idx = blockIdx.x * blockDim.x + threadIdx.x;
    if (idx >= 80 * 4096) return;
    float v = wm0[idx];
    __nv_bfloat16 hi = __float2bfloat16_rn(v);
    __nv_bfloat16 lo = __float2bfloat16_rn(v - __bfloat162float(hi));
    g_wHi[idx] = hi;
    g_wLo[idx] = lo;
}

// ---------------------------------------------------------------------------
// Kernel G: fused 4-layer gaussian stack.
// 1 block = 16 samples processed as TWO independent streams of 8 samples
// (512 threads: sub = tid>>8 picks the stream, t = tid&255 is the worker id).
// Reordered algebra: since rows of K sum to 1, K@(xW+b) = (K@x)W + b; layer 0
// keeps original order (shrink channels first). Mixes use banded K.
// Shared (floats): sK 4*64*65 @0 | W0t@16640 W1t@17152 W2t@17280 W3t@17792 |
// B0..B3 @19840.. | per-stream bufA/bufB (64x68) @19960 (+8704 per stream).
// Total 37368 floats = 149472 B dynamic.
// ---------------------------------------------------------------------------
__global__ __launch_bounds__(512) void kernG(
    const float* __restrict__ x,
    const float* __restrict__ w0, const float* __restrict__ b0,
    const float* __restrict__ w1, const float* __restrict__ b1,
    const float* __restrict__ w2, const float* __restrict__ b2,
    const float* __restrict__ w3, const float* __restrict__ b3)
{
    extern __shared__ __align__(16) float sm[];
    float* sK  = sm;
    float* sW0 = sm + 16640;
    float* sW1 = sm + 17152;
    float* sW2 = sm + 17280;
    float* sW3 = sm + 17792;
    float* sB0 = sm + 19840;
    float* sB1 = sm + 19848;
    float* sB2 = sm + 19864;
    float* sB3 = sm + 19896;

    const int tid = threadIdx.x;
    const int sub = tid >> 8;
    const int t   = tid & 255;
    float* bufA = sm + 19960 + sub * 8704;
    float* bufB = bufA + 4352;

    const int R0 = g_band[0], R1 = g_band[1], R2 = g_band[2], R3 = g_band[3];

    // stage kernels (stride 65) + transposed weights + biases (512 threads)
    for (int idx = tid; idx < 4 * 64 * 64; idx += 512) {
        int l = idx >> 12, rem = idx & 4095;
        int i = rem >> 6, j = rem & 63;
        sK[l * 4160 + i * 65 + j] = g_K[idx];
    }
    for (int idx = tid; idx < 8 * 64;  idx += 512) { int o = idx >> 6, c = idx & 63; sW0[c * 8  + o] = w0[idx]; }
    for (int idx = tid; idx < 16 * 8;  idx += 512) { int o = idx >> 3, c = idx & 7;  sW1[c * 16 + o] = w1[idx]; }
    for (int idx = tid; idx < 32 * 16; idx += 512) { int o = idx >> 4, c = idx & 15; sW2[c * 32 + o] = w2[idx]; }
    for (int idx = tid; idx < 64 * 32; idx += 512) { int o = idx >> 5, c = idx & 31; sW3[c * 64 + o] = w3[idx]; }
    if (tid < 8)  sB0[tid] = b0[tid];
    else if (tid >= 32 && tid < 48) sB1[tid - 32] = b1[tid - 32];
    else if (tid >= 64 && tid < 96) sB2[tid - 64] = b2[tid - 64];
    else if (tid >= 128 && tid < 192) sB3[tid - 128] = b3[tid - 128];
    __syncthreads();

    for (int s = 0; s < 8; s++) {
        const size_t b = (size_t)blockIdx.x * 16 + sub * 8 + s;

        // load x[b] (64x64) into bufA
        {
            const float4* xb = (const float4*)(x + b * 4096);
            for (int idx = t; idx < 1024; idx += 256) {
                int r = idx >> 4, c4 = idx & 15;
                *(float4*)(bufA + r * 68 + c4 * 4) = xb[idx];
            }
        }
        __syncthreads();

        // ---- L0 wmult: bufB[j][0..7] = bufA[j][:] @ W0t + b0 (no act yet)
        {
            int j = t >> 2, o0 = (t & 3) * 2;
            float a0 = sB0[o0], a1 = sB0[o0 + 1];
            const float* Ar = bufA + j * 68;
            #pragma unroll 8
            for (int c = 0; c < 64; c++) {
                float xv = Ar[c];
                a0 = fmaf(xv, sW0[c * 8 + o0], a0);
                a1 = fmaf(xv, sW0[c * 8 + o0 + 1], a1);
            }
            bufB[j * 68 + o0] = a0; bufB[j * 68 + o0 + 1] = a1;
        }
        __syncthreads();

        // ---- L0 mix + leaky: bufA = leaky(K0 @ bufB)   (C=8, banded)
        {
            int i = t >> 2, o0 = (t & 3) * 2;
            const float* Ki = sK + i * 65;
            int jlo = i - R0; if (jlo < 0) jlo = 0;
            int jhi = i + R0; if (jhi > 63) jhi = 63;
            float a0 = 0.f, a1 = 0.f;
            #pragma unroll 4
            for (int j = jlo; j <= jhi; j++) {
                float kv = Ki[j];
                float2 tv = *(const float2*)(bufB + j * 68 + o0);
                a0 = fmaf(kv, tv.x, a0);
                a1 = fmaf(kv, tv.y, a1);
            }
            a0 = a0 > 0.f ? a0 : a0 * NEG;
            a1 = a1 > 0.f ? a1 : a1 * NEG;
            bufA[i * 68 + o0] = a0; bufA[i * 68 + o0 + 1] = a1;
        }
        __syncthreads();

        // ---- L1 mix: bufB = K1 @ bufA   (C=8, banded, no act)
        {
            int i = t >> 2, o0 = (t & 3) * 2;
            const float* Ki = sK + 4160 + i * 65;
            int jlo = i - R1; if (jlo < 0) jlo = 0;
            int jhi = i + R1; if (jhi > 63) jhi = 63;
            float a0 = 0.f, a1 = 0.f;
            #pragma unroll 4
            for (int j = jlo; j <= jhi; j++) {
                float kv = Ki[j];
                float2 tv = *(const float2*)(bufA + j * 68 + o0);
                a0 = fmaf(kv, tv.x, a0);
                a1 = fmaf(kv, tv.y, a1);
            }
            bufB[i * 68 + o0] = a0; bufB[i * 68 + o0 + 1] = a1;
        }
        __syncthreads();

        // ---- L1 wmult + leaky: bufA[j][0..15] = leaky(bufB[j][:8] @ W1t + b1)
        {
            int j0 = (t >> 3) * 2, o0 = (t & 7) * 2;
            float a00 = sB1[o0], a01 = sB1[o0 + 1];
            float a10 = a00, a11 = a01;
            #pragma unroll
            for (int c = 0; c < 8; c++) {
                float i0 = bufB[j0 * 68 + c], i1 = bufB[(j0 + 1) * 68 + c];
                float wv0 = sW1[c * 16 + o0], wv1 = sW1[c * 16 + o0 + 1];
                a00 = fmaf(i0, wv0, a00); a01 = fmaf(i0, wv1, a01);
                a10 = fmaf(i1, wv0, a10); a11 = fmaf(i1, wv1, a11);
            }
            a00 = a00 > 0.f ? a00 : a00 * NEG; a01 = a01 > 0.f ? a01 : a01 * NEG;
            a10 = a10 > 0.f ? a10 : a10 * NEG; a11 = a11 > 0.f ? a11 : a11 * NEG;
            bufA[j0 * 68 + o0] = a00;       bufA[j0 * 68 + o0 + 1] = a01;
            bufA[(j0 + 1) * 68 + o0] = a10; bufA[(j0 + 1) * 68 + o0 + 1] = a11;
        }
        __syncthreads();

        // ---- L2 mix: bufB = K2 @ bufA  (C=16, banded), 2i x 2o
        {
            int i0 = (t >> 3) * 2, o0 = (t & 7) * 2;
            const float* K0r = sK + 2 * 4160 + i0 * 65;
            const float* K1r = K0r + 65;
            int jlo = i0 - R2; if (jlo < 0) jlo = 0;
            int jhi = i0 + 1 + R2; if (jhi > 63) jhi = 63;
            float a00 = 0.f, a01 = 0.f, a10 = 0.f, a11 = 0.f;
            #pragma unroll 4
            for (int j = jlo; j <= jhi; j++) {
                float2 tv = *(const float2*)(bufA + j * 68 + o0);
                float k0 = K0r[j], k1 = K1r[j];
                a00 = fmaf(k0, tv.x, a00); a01 = fmaf(k0, tv.y, a01);
                a10 = fmaf(k1, tv.x, a10); a11 = fmaf(k1, tv.y, a11);
            }
            bufB[i0 * 68 + o0] = a00;       bufB[i0 * 68 + o0 + 1] = a01;
            bufB[(i0 + 1) * 68 + o0] = a10; bufB[(i0 + 1) * 68 + o0 + 1] = a11;
        }
        __syncthreads();

        // ---- L2 wmult + leaky: bufA[j][0..31] = leaky(bufB[j][:16] @ W2t + b2)
        {
            int j0 = (t >> 4) * 4, o0 = (t & 15) * 2;
            float acc[4][2];
            #pragma unroll
            for (int jj = 0; jj < 4; jj++) { acc[jj][0] = sB2[o0]; acc[jj][1] = sB2[o0 + 1]; }
            #pragma unroll
            for (int c = 0; c < 16; c++) {
                float wv0 = sW2[c * 32 + o0], wv1 = sW2[c * 32 + o0 + 1];
                #pragma unroll
                for (int jj = 0; jj < 4; jj++) {
                    float iv = bufB[(j0 + jj) * 68 + c];
                    acc[jj][0] = fmaf(iv, wv0, acc[jj][0]);
                    acc[jj][1] = fmaf(iv, wv1, acc[jj][1]);
                }
            }
            #pragma unroll
            for (int jj = 0; jj < 4; jj++) {
                float v0 = acc[jj][0], v1 = acc[jj][1];
                v0 = v0 > 0.f ? v0 : v0 * NEG;
                v1 = v1 > 0.f ? v1 : v1 * NEG;
                bufA[(j0 + jj) * 68 + o0] = v0;
                bufA[(j0 + jj) * 68 + o0 + 1] = v1;
            }
        }
        __syncthreads();

        // ---- L3 mix: bufB = K3 @ bufA  (C=32, banded), 4i x 2o
        {
            int i0 = (t >> 4) * 4, o0 = (t & 15) * 2;
            const float* Kb = sK + 3 * 4160;
            int jlo = i0 - R3; if (jlo < 0) jlo = 0;
            int jhi = i0 + 3 + R3; if (jhi > 63) jhi = 63;
            float acc[4][2] = {{0.f,0.f},{0.f,0.f},{0.f,0.f},{0.f,0.f}};
            #pragma unroll 4
            for (int j = jlo; j <= jhi; j++) {
                float2 tv = *(const float2*)(bufA + j * 68 + o0);
                #pragma unroll
                for (int ii = 0; ii < 4; ii++) {
                    float kv = Kb[(i0 + ii) * 65 + j];
                    acc[ii][0] = fmaf(kv, tv.x, acc[ii][0]);
                    acc[ii][1] = fmaf(kv, tv.y, acc[ii][1]);
                }
            }
            #pragma unroll
            for (int ii = 0; ii < 4; ii++) {
                bufB[(i0 + ii) * 68 + o0] = acc[ii][0];
                bufB[(i0 + ii) * 68 + o0 + 1] = acc[ii][1];
            }
        }
        __syncthreads();

        // ---- L3 wmult + leaky: bufA[j][0..63] = leaky(bufB[j][:32] @ W3t + b3)
        {
            int j0 = (t >> 4) * 4, o0 = (t & 15) * 4;
            float acc[4][4];
            #pragma unroll
            for (int jj = 0; jj < 4; jj++)
                #pragma unroll
                for (int oo = 0; oo < 4; oo++)
                    acc[jj][oo] = sB3[o0 + oo];
            #pragma unroll
            for (int c = 0; c < 32; c++) {
                float4 wv = *(const float4*)(sW3 + c * 64 + o0);
                #pragma unroll
                for (int jj = 0; jj < 4; jj++) {
                    float iv = bufB[(j0 + jj) * 68 + c];
                    acc[jj][0] = fmaf(iv, wv.x, acc[jj][0]);
                    acc[jj][1] = fmaf(iv, wv.y, acc[jj][1]);
                    acc[jj][2] = fmaf(iv, wv.z, acc[jj][2]);
                    acc[jj][3] = fmaf(iv, wv.w, acc[jj][3]);
                }
            }
            #pragma unroll
            for (int jj = 0; jj < 4; jj++) {
                float4 v;
                v.x = acc[jj][0] > 0.f ? acc[jj][0] : acc[jj][0] * NEG;
                v.y = acc[jj][1] > 0.f ? acc[jj][1] : acc[jj][1] * NEG;
                v.z = acc[jj][2] > 0.f ? acc[jj][2] : acc[jj][2] * NEG;
                v.w = acc[jj][3] > 0.f ? acc[jj][3] : acc[jj][3] * NEG;
                *(float4*)(bufA + (j0 + jj) * 68 + o0) = v;
            }
        }
        __syncthreads();

        // write to scratch as split bf16 hi/lo [b][4096]
        {
            for (int idx = t; idx < 2048; idx += 256) {
                int r = idx >> 5, c2 = idx & 31;
                float2 v = *(const float2*)(bufA + r * 68 + c2 * 2);
                __nv_bfloat16 h0 = __float2bfloat16_rn(v.x);
                __nv_bfloat16 h1 = __float2bfloat16_rn(v.y);
                __nv_bfloat16 l0 = __float2bfloat16_rn(v.x - __bfloat162float(h0));
                __nv_bfloat16 l1 = __float2bfloat16_rn(v.y - __bfloat162float(h1));
                __nv_bfloat162 ph; ph.x = h0; ph.y = h1;
                __nv_bfloat162 pl; pl.x = l0; pl.y = l1;
                *(__nv_bfloat162*)(g_hHi + b * 4096 + r * 64 + c2 * 2) = ph;
                *(__nv_bfloat162*)(g_hLo + b * 4096 + r * 64 + c2 * 2) = pl;
            }
        }
        __syncthreads();
    }
}

// ---------------------------------------------------------------------------
// Kernel C: tensor-core compress MLP.
// Layer1: out1 = leaky(H @ wm0T + bm0), split-bf16 (Ah*Bh + Ah*Bl + Al*Bh)
// via mma.sync.m16n8k16, fp32 accum -> ~1e-5 rel error.
// Block: 128 rows x 80 cols, K-chunks of 64, cp.async double-buffered.
// 8 warps: (wm 0..3) x (wn 0..1); warp tile 32x40 (2 m16 x 5 n8).
// Layer2: out = leaky(out1 @ wm1T + bm1) in fp32 SIMT (tiny).
// ---------------------------------------------------------------------------
#define KC_STAGE_H   29952               // halves per stage
#define KC_SA_H      0                   // sA hi offset (halves)
#define KC_SA_L      9216
#define KC_SW_H      18432
#define KC_SW_L      24192
#define KC_F32_OFF   119808              // bytes: start of persistent fp32 region
#define KC_SMEM_BYTES (119808 + 21056)

__device__ __forceinline__ void kc_ldmatrix_x4(unsigned& r0, unsigned& r1,
                                               unsigned& r2, unsigned& r3,
                                               const __nv_bfloat16* p) {
    unsigned addr = (unsigned)__cvta_generic_to_shared(p);
    asm volatile("ldmatrix.sync.aligned.m8n8.x4.shared.b16 {%0,%1,%2,%3}, [%4];"
                 : "=r"(r0), "=r"(r1), "=r"(r2), "=r"(r3) : "r"(addr));
}
__device__ __forceinline__ void kc_ldmatrix_x2(unsigned& r0, unsigned& r1,
                                               const __nv_bfloat16* p) {
    unsigned addr = (unsigned)__cvta_generic_to_shared(p);
    asm volatile("ldmatrix.sync.aligned.m8n8.x2.shared.b16 {%0,%1}, [%2];"
                 : "=r"(r0), "=r"(r1) : "r"(addr));
}
__device__ __forceinline__ void kc_mma(float* c, unsigned a0, unsigned a1,
                                       unsigned a2, unsigned a3,
                                       unsigned b0, unsigned b1) {
    asm volatile("mma.sync.aligned.m16n8k16.row.col.f32.bf16.bf16.f32 "
                 "{%0,%1,%2,%3}, {%4,%5,%6,%7}, {%8,%9}, {%0,%1,%2,%3};"
                 : "+f"(c[0]), "+f"(c[1]), "+f"(c[2]), "+f"(c[3])
                 : "r"(a0), "r"(a1), "r"(a2), "r"(a3), "r"(b0), "r"(b1));
}
__device__ __forceinline__ void kc_cpasync16(__nv_bfloat16* dst, const __nv_bfloat16* src) {
    unsigned d = (unsigned)__cvta_generic_to_shared(dst);
    asm volatile("cp.async.cg.shared.global [%0], [%1], 16;" :: "r"(d), "l"(src));
}

__global__ __launch_bounds__(256) void kernC(const float* __restrict__ bm0,
                                             const float* __restrict__ wm1,
                                             const float* __restrict__ bm1,
                                             float* __restrict__ out)
{
    extern __shared__ __align__(16) char smc[];
    __nv_bfloat16* sh = (__nv_bfloat16*)smc;
    float* fpers = (float*)(smc + KC_F32_OFF);
    float* sWm1t = fpers;            // [80][64] (pad 64)
    float* sBm0  = fpers + 5120;     // 80
    float* sBm1  = fpers + 5200;     // 60
    float* sOut1 = (float*)smc;      // [128][84] reuses tile region after k-loop

    const int tid  = threadIdx.x;
    const int lane = tid & 31;
    const int warp = tid >> 5;
    const int wm = warp >> 1, wn = warp & 1;
    const int m0 = blockIdx.x * 128;

    // persistent staging: wm1 transposed + biases
    for (int idx = tid; idx < 4800; idx += 256) {
        int o = idx / 80, c = idx % 80;
        sWm1t[c * 64 + o] = wm1[idx];
    }
    if (tid < 80) sBm0[tid] = bm0[tid];
    if (tid < 60) sBm1[tid] = bm1[tid];

    // cp.async stage loader
    auto load_stage = [&](int kb, int st) {
        __nv_bfloat16* base = sh + st * KC_STAGE_H;
        const size_t kcol = (size_t)kb * 64;
        #pragma unroll
        for (int c = tid; c < 1024; c += 256) {
            int r = c >> 3, o = c & 7;
            kc_cpasync16(base + KC_SA_H + r * 72 + o * 8,
                         g_hHi + (size_t)(m0 + r) * 4096 + kcol + o * 8);
        }
        #pragma unroll
        for (int c = tid; c < 1024; c += 256) {
            int r = c >> 3, o = c & 7;
            kc_cpasync16(base + KC_SA_L + r * 72 + o * 8,
                         g_hLo + (size_t)(m0 + r) * 4096 + kcol + o * 8);
        }
        for (int c = tid; c < 640; c += 256) {
            int r = c >> 3, o = c & 7;
            kc_cpasync16(base + KC_SW_H + r * 72 + o * 8,
                         g_wHi + (size_t)r * 4096 + kcol + o * 8);
        }
        for (int c = tid; c < 640; c += 256) {
            int r = c >> 3, o = c & 7;
            kc_cpasync16(base + KC_SW_L + r * 72 + o * 8,
                         g_wLo + (size_t)r * 4096 + kcol + o * 8);
        }
    };

    float acc[2][5][4];
    #pragma unroll
    for (int i = 0; i < 2; i++)
        #pragma unroll
        for (int j = 0; j < 5; j++)
            #pragma unroll
            for (int k = 0; k < 4; k++) acc[i][j][k] = 0.f;

    load_stage(0, 0);
    asm volatile("cp.async.commit_group;");

    // precomputed lane offsets
    const int aq  = lane >> 3;          // 0..3 matrix id
    const int arn = lane & 7;
    const int a_row_off = (aq & 1) * 8 + arn;   // within m16
    const int a_col_off = (aq >> 1) * 8;        // within k16
    const int bl  = lane & 15;
    const int b_rn = bl & 7;
    const int b_hi8 = (bl >> 3) * 8;

    const int NK = 64;
    for (int kb = 0; kb < NK; kb++) {
        if (kb + 1 < NK) {
            load_stage(kb + 1, (kb + 1) & 1);
            asm volatile("cp.async.commit_group;");
            asm volatile("cp.async.wait_group 1;");
        } else {
            asm volatile("cp.async.wait_group 0;");
        }
        __syncthreads();

        __nv_bfloat16* base = sh + (kb & 1) * KC_STAGE_H;
        __nv_bfloat16* sAh = base + KC_SA_H;
        __nv_bfloat16* sAl = base + KC_SA_L;
        __nv_bfloat16* sWh = base + KC_SW_H;
        __nv_bfloat16* sWl = base + KC_SW_L;

        #pragma unroll
        for (int sub = 0; sub < 4; sub++) {
            const int kc = sub * 16;
            // B fragments: 5 ntiles x {hi, lo}
            unsigned bh[5][2], blo[5][2];
            #pragma unroll
            for (int n = 0; n < 5; n++) {
                const int brow = wn * 40 + n * 8 + b_rn;
                kc_ldmatrix_x2(bh[n][0],  bh[n][1],  sWh + brow * 72 + kc + b_hi8);
                kc_ldmatrix_x2(blo[n][0], blo[n][1], sWl + brow * 72 + kc + b_hi8);
            }
            #pragma unroll
            for (int tmt = 0; tmt < 2; tmt++) {
                const int arow = wm * 32 + tmt * 16 + a_row_off;
                unsigned ah0, ah1, ah2, ah3, al0, al1, al2, al3;
                kc_ldmatrix_x4(ah0, ah1, ah2, ah3, sAh + arow * 72 + kc + a_col_off);
                kc_ldmatrix_x4(al0, al1, al2, al3, sAl + arow * 72 + kc + a_col_off);
                #pragma unroll
                for (int n = 0; n < 5; n++) {
                    kc_mma(acc[tmt][n], ah0, ah1, ah2, ah3, bh[n][0],  bh[n][1]);
                    kc_mma(acc[tmt][n], ah0, ah1, ah2, ah3, blo[n][0], blo[n][1]);
                    kc_mma(acc[tmt][n], al0, al1, al2, al3, bh[n][0],  bh[n][1]);
                }
            }
        }
        __syncthreads();
    }

    // epilogue layer 1: bias + leaky -> sOut1[128][84]
    #pragma unroll
    for (int tmt = 0; tmt < 2; tmt++)
        #pragma unroll
        for (int n = 0; n < 5; n++)
            #pragma unroll
            for (int cr = 0; cr < 4; cr++) {
                int row = wm * 32 + tmt * 16 + (lane >> 2) + ((cr >= 2) ? 8 : 0);
                int col = wn * 40 + n * 8 + (lane & 3) * 2 + (cr & 1);
                float v = acc[tmt][n][cr] + sBm0[col];
                v = v > 0.f ? v : v * NEG;
                sOut1[row * 84 + col] = v;
            }
    __syncthreads();

    // layer 2: out[128][60] = leaky(out1 @ wm1T + bm1)
    {
        const int tr = tid >> 4;       // 0..15, rows tr + 16*i
        const int tc = tid & 15;       // cols tc*4 .. tc*4+3 (guard >=60)
        float a2[8][4];
        #pragma unroll
        for (int i = 0; i < 8; i++)
            #pragma unroll
            for (int j = 0; j < 4; j++) a2[i][j] = 0.f;
        for (int c = 0; c < 80; c++) {
            float wv[4];
            #pragma unroll
            for (int j = 0; j < 4; j++) {
                int o = tc * 4 + j;
                wv[j] = (o < 60) ? sWm1t[c * 64 + o] : 0.f;
            }
            #pragma unroll
            for (int i = 0; i < 8; i++) {
                float cv = sOut1[(tr + 16 * i) * 84 + c];
                #pragma unroll
                for (int j = 0; j < 4; j++)
                    a2[i][j] = fmaf(cv, wv[j], a2[i][j]);
            }
        }
        #pragma unroll
        for (int i = 0; i < 8; i++)
            #pragma unroll
            for (int j = 0; j < 4; j++) {
                int o = tc * 4 + j;
                if (o < 60) {
                    float v = a2[i][j] + sBm1[o];
                    v = v > 0.f ? v : v * NEG;
                    out[(size_t)(m0 + tr + 16 * i) * 60 + o] = v;
                }
            }
    }
}

// ---------------------------------------------------------------------------
extern "C" void kernel_launch(void* const* d_in, const int* in_sizes, int n_in,
                              void* d_out, int out_size) {
    (void)in_sizes; (void)n_in; (void)out_size;
    const float* x   = (const float*)d_in[0];
    const float* w0  = (const float*)d_in[1];
    const float* b0  = (const float*)d_in[2];
    const float* s0  = (const float*)d_in[3];
    const float* w1  = (const float*)d_in[4];
    const float* b1  = (const float*)d_in[5];
    const float* s1  = (const float*)d_in[6];
    const float* w2  = (const float*)d_in[7];
    const float* b2  = (const float*)d_in[8];
    const float* s2  = (const float*)d_in[9];
    const float* w3  = (const float*)d_in[10];
    const float* b3  = (const float*)d_in[11];
    const float* s3  = (const float*)d_in[12];
    const float* wm0 = (const float*)d_in[13];
    const float* bm0 = (const float*)d_in[14];
    const float* wm1 = (const float*)d_in[15];
    const float* bm1 = (const float*)d_in[16];
    float* out = (float*)d_out;

    static int attr_done = 0;
    if (!attr_done) {
        cudaFuncSetAttribute(kernG, cudaFuncAttributeMaxDynamicSharedMemorySize, 149472);
        cudaFuncSetAttribute(kernC, cudaFuncAttributeMaxDynamicSharedMemorySize, KC_SMEM_BYTES);
        attr_done = 1;
    }

    kernK<<<1, 256>>>(s0, s1, s2, s3);
    kernT<<<1280, 256>>>(wm0);
    kernG<<<1024, 512, 149472>>>(x, w0, b0, w1, b1, w2, b2, w3, b3);
    kernC<<<128, 256, KC_SMEM_BYTES>>>(bm0, wm1, bm1, out);
}

// round 5
// speedup vs baseline: 1.1046x; 1.0968x over previous
#include <cuda_runtime.h>
#include <cuda_bf16.h>
#include <math.h>

#define NEG 0.01f
typedef __nv_bfloat16 bf16;

// ---------------------------------------------------------------------------
// Scratch (allocation-free rule: __device__ globals)
// ---------------------------------------------------------------------------
__device__ __align__(16) float g_K[4 * 64 * 64];      // 4 normalized gaussian kernels
__device__ int g_band[4];                             // band radius per layer
__device__ __align__(16) bf16 g_wHi[80 * 4096];       // wm0 split hi [o][k]
__device__ __align__(16) bf16 g_wLo[80 * 4096];       // wm0 split lo
__device__ __align__(16) bf16 g_hHi[(size_t)16384 * 4096]; // H split hi [b][k]
__device__ __align__(16) bf16 g_hLo[(size_t)16384 * 4096]; // H split lo

// ---------------------------------------------------------------------------
// Kernel K: build 4 L1-normalized gaussian mixing matrices + band radii
// ---------------------------------------------------------------------------
__global__ void kernK(const float* __restrict__ s0, const float* __restrict__ s1,
                      const float* __restrict__ s2, const float* __restrict__ s3) {
    int t = threadIdx.x;              // 256 threads = 4 layers * 64 rows
    int l = t >> 6, i = t & 63;
    float sg = (l == 0) ? s0[0] : (l == 1) ? s1[0] : (l == 2) ? s2[0] : s3[0];
    float denom = 2.0f * sg * sg;
    float sum = 0.0f;
    for (int j = 0; j < 64; j++) {
        float d = (float)(i - j);
        sum += expf(-(d * d) / denom);
    }
    sum = fmaxf(sum, 1e-12f);
    for (int j = 0; j < 64; j++) {
        float d = (float)(i - j);
        g_K[(l * 64 + i) * 64 + j] = expf(-(d * d) / denom) / sum;
    }
    if (i == 0) {
        float rr = sqrtf(fmaxf(denom, 0.0f) * 18.5f);
        int R = (int)rr + 1;
        if (R > 63) R = 63;
        g_band[l] = R;
    }
}

// ---------------------------------------------------------------------------
// Kernel T: split wm0 [80][4096] fp32 -> bf16 hi/lo (same layout)
// ---------------------------------------------------------------------------
__global__ void kernT(const float* __restrict__ wm0) {
    int idx = blockIdx.x * blockDim.x + threadIdx.x;
    if (idx >= 80 * 4096) return;
    float v = wm0[idx];
    bf16 hi = __float2bfloat16_rn(v);
    bf16 lo = __float2bfloat16_rn(v - __bfloat162float(hi));
    g_wHi[idx] = hi;
    g_wLo[idx] = lo;
}

// ---------------------------------------------------------------------------
// mma helpers
// ---------------------------------------------------------------------------
__device__ __forceinline__ void ldx4(unsigned r[4], const bf16* p) {
    unsigned a = (unsigned)__cvta_generic_to_shared(p);
    asm volatile("ldmatrix.sync.aligned.m8n8.x4.shared.b16 {%0,%1,%2,%3}, [%4];"
                 : "=r"(r[0]), "=r"(r[1]), "=r"(r[2]), "=r"(r[3]) : "r"(a));
}
__device__ __forceinline__ void ldx2(unsigned r[2], const bf16* p) {
    unsigned a = (unsigned)__cvta_generic_to_shared(p);
    asm volatile("ldmatrix.sync.aligned.m8n8.x2.shared.b16 {%0,%1}, [%2];"
                 : "=r"(r[0]), "=r"(r[1]) : "r"(a));
}
__device__ __forceinline__ void ldx2t(unsigned r[2], const bf16* p) {
    unsigned a = (unsigned)__cvta_generic_to_shared(p);
    asm volatile("ldmatrix.sync.aligned.m8n8.x2.trans.shared.b16 {%0,%1}, [%2];"
                 : "=r"(r[0]), "=r"(r[1]) : "r"(a));
}
__device__ __forceinline__ void hmma(float c[4], const unsigned a[4], const unsigned b[2]) {
    asm volatile("mma.sync.aligned.m16n8k16.row.col.f32.bf16.bf16.f32 "
                 "{%0,%1,%2,%3}, {%4,%5,%6,%7}, {%8,%9}, {%0,%1,%2,%3};"
                 : "+f"(c[0]), "+f"(c[1]), "+f"(c[2]), "+f"(c[3])
                 : "r"(a[0]), "r"(a[1]), "r"(a[2]), "r"(a[3]), "r"(b[0]), "r"(b[1]));
}
__device__ __forceinline__ float lrelu(float v) { return v > 0.f ? v : v * NEG; }
__device__ __forceinline__ void bsplit(bf16* hp, bf16* lp, float v) {
    bf16 h = __float2bfloat16_rn(v);
    *hp = h;
    *lp = __float2bfloat16_rn(v - __bfloat162float(h));
}

// Accumulate one 16x8 tile over k-tiles [ktlo..kthi] with 3-term split:
// hh += Ah*Bh, hl += Ah*Bl, lh += Al*Bh. BT: B stored [K][N] (use trans).
template <bool BT>
__device__ __forceinline__ void tile3(float hh[4], float hl[4], float lh[4],
                                      const bf16* Ah, const bf16* Al, int lda, int m0,
                                      const bf16* Bh, const bf16* Bl, int ldb, int n0,
                                      int ktlo, int kthi, int lane) {
    const int arow = m0 + (lane & 7) + ((lane >> 3) & 1) * 8;
    const int acol = (lane >> 4) * 8;
    for (int kt = ktlo; kt <= kthi; kt++) {
        const int kc = kt * 16;
        unsigned a0[4], a1[4], b0[2], b1[2];
        ldx4(a0, Ah + arow * lda + kc + acol);
        ldx4(a1, Al + arow * lda + kc + acol);
        if (BT) {
            const int br = kc + (lane & 15);
            ldx2t(b0, Bh + br * ldb + n0);
            ldx2t(b1, Bl + br * ldb + n0);
        } else {
            const int br = n0 + (lane & 7);
            const int bc = kc + ((lane >> 3) & 1) * 8;
            ldx2(b0, Bh + br * ldb + bc);
            ldx2(b1, Bl + br * ldb + bc);
        }
        hmma(hh, a0, b0);
        hmma(hl, a0, b1);
        hmma(lh, a1, b0);
    }
}

// ---------------------------------------------------------------------------
// Kernel G (tensor-core): fused 4-layer gaussian stack.
// 256 threads / 8 warps per block; block processes 16 samples as 8 groups
// of S=2. Reordered algebra (rows of K sum to 1): layer0 = leaky(K0@(xW0+b0)),
// layers 1..3 = leaky((Kl@T)Wl + bl). All ops are split-bf16 mma.
//
// SMEM (halves): K hi/lo 4x[64][72] | R1 A-layout [128][72] hi/lo (X, L3m out)
// | R2, R3: 10240-half regions (B-layout 64x72 hi/lo, or A-layout 128x40
// hi/lo, or one out plane 128x72) | weights hi/lo | fp32 biases.
// ---------------------------------------------------------------------------
#define OKH   0
#define OKL   18432
#define OR1H  36864
#define OR1L  46080
#define OR2   55296
#define OR3   65536
#define OW0H  75776
#define OW0L  76352
#define OW1H  76928
#define OW1L  77184
#define OW2H  77440
#define OW2L  77952
#define OW3H  78464
#define OW3L  81024
#define OHALVES 83584
#define KG_SMEM_BYTES (OHALVES * 2 + 480)
// R2/R3 sub-offsets: B-layout hi +0 / lo +4608 ; A-layout hi +0 / lo +5120

__global__ __launch_bounds__(256) void kernG(
    const float* __restrict__ x,
    const float* __restrict__ w0, const float* __restrict__ b0,
    const float* __restrict__ w1, const float* __restrict__ b1,
    const float* __restrict__ w2, const float* __restrict__ b2,
    const float* __restrict__ w3, const float* __restrict__ b3)
{
    extern __shared__ __align__(16) bf16 sm[];
    float* sBias = (float*)(sm + OHALVES);   // b0@0, b1@8, b2@24, b3@56

    const int tid = threadIdx.x;
    const int lane = tid & 31;
    const int warp = tid >> 5;
    const int R0 = g_band[0], R1b = g_band[1], R2b = g_band[2], R3b = g_band[3];

    // ---- one-time staging ----
    for (int idx = tid; idx < 16384; idx += 256) {
        int l = idx >> 12, i = (idx >> 6) & 63, j = idx & 63;
        bsplit(sm + OKH + l * 4608 + i * 72 + j, sm + OKL + l * 4608 + i * 72 + j, g_K[idx]);
    }
    for (int idx = tid; idx < 512; idx += 256) {    // w0 [8][64] -> [8][72]
        int o = idx >> 6, c = idx & 63;
        bsplit(sm + OW0H + o * 72 + c, sm + OW0L + o * 72 + c, w0[idx]);
    }
    if (tid < 256) {                                // w1 [16][8] -> [16][16] k-padded
        int o = tid >> 4, c = tid & 15;
        float v = (c < 8) ? w1[o * 8 + c] : 0.f;
        bsplit(sm + OW1H + o * 16 + c, sm + OW1L + o * 16 + c, v);
    }
    for (int idx = tid; idx < 512; idx += 256) {    // w2 [32][16]
        int o = idx >> 4, c = idx & 15;
        bsplit(sm + OW2H + o * 16 + c, sm + OW2L + o * 16 + c, w2[idx]);
    }
    for (int idx = tid; idx < 2048; idx += 256) {   // w3 [64][32] -> [64][40]
        int o = idx >> 5, c = idx & 31;
        bsplit(sm + OW3H + o * 40 + c, sm + OW3L + o * 40 + c, w3[idx]);
    }
    if (tid < 8) sBias[tid] = b0[tid];
    else if (tid >= 32 && tid < 48) sBias[8 + tid - 32] = b1[tid - 32];
    else if (tid >= 64 && tid < 96) sBias[24 + tid - 64] = b2[tid - 64];
    else if (tid >= 128 && tid < 192) sBias[56 + tid - 128] = b3[tid - 128];
    __syncthreads();

    const int erow = lane >> 2;           // epilogue base row
    const int ecol = (lane & 3) * 2;      // epilogue base col

    for (int g = 0; g < 8; g++) {
        const int gb = blockIdx.x * 16 + g * 2;

        // ---- X load + split -> R1 (A-layout [s*64+h][72]) ----
        {
            const float4* xb = (const float4*)x;
            for (int idx = tid; idx < 2048; idx += 256) {
                int s = idx >> 10, rem = idx & 1023;
                int h = rem >> 4, c4 = rem & 15;
                float4 v = xb[(size_t)(gb + s) * 1024 + rem];
                bf16* hp = sm + OR1H + (s * 64 + h) * 72 + c4 * 4;
                bf16* lp = sm + OR1L + (s * 64 + h) * 72 + c4 * 4;
                bsplit(hp + 0, lp + 0, v.x); bsplit(hp + 1, lp + 1, v.y);
                bsplit(hp + 2, lp + 2, v.z); bsplit(hp + 3, lp + 3, v.w);
            }
        }
        __syncthreads();

        // ---- G0: L0 wmult  M=128 K=64 N=8 : X@W0 + b0 -> R2.B [h][s*8+c]
        {
            const int m0 = warp * 16;
            float hh[4] = {0,0,0,0}, hl[4] = {0,0,0,0}, lh[4] = {0,0,0,0};
            tile3<false>(hh, hl, lh, sm + OR1H, sm + OR1L, 72, m0,
                         sm + OW0H, sm + OW0L, 72, 0, 0, 3, lane);
            #pragma unroll
            for (int cr = 0; cr < 4; cr++) {
                int row = m0 + erow + ((cr & 2) << 2);
                int col = ecol + (cr & 1);
                float v = hh[cr] + hl[cr] + lh[cr] + sBias[col];
                int s = row >> 6, h = row & 63;
                int o = h * 72 + s * 8 + col;
                bsplit(sm + OR2 + o, sm + OR2 + 4608 + o, v);
            }
        }
        __syncthreads();

        // ---- G1: L0 mix  leaky(K0 @ R2) -> R3.B   M=64 N=16 (banded)
        {
            const int mt = warp >> 1, nt = warp & 1;
            const int m0 = mt * 16, n0 = nt * 8;
            int ktlo = max(0, m0 - R0) >> 4, kthi = min(63, m0 + 15 + R0) >> 4;
            float hh[4] = {0,0,0,0}, hl[4] = {0,0,0,0}, lh[4] = {0,0,0,0};
            tile3<true>(hh, hl, lh, sm + OKH, sm + OKL, 72, m0,
                        sm + OR2, sm + OR2 + 4608, 72, n0, ktlo, kthi, lane);
            #pragma unroll
            for (int cr = 0; cr < 4; cr++) {
                int row = m0 + erow + ((cr & 2) << 2);
                int n = n0 + ecol + (cr & 1);
                float v = lrelu(hh[cr] + hl[cr] + lh[cr]);
                bsplit(sm + OR3 + row * 72 + n, sm + OR3 + 4608 + row * 72 + n, v);
            }
        }
        __syncthreads();

        // ---- G2: L1 mix  K1 @ R3 -> R2.A [s*64+h][c] (+zero pad c8..15)
        {
            const int mt = warp >> 1, nt = warp & 1;
            const int m0 = mt * 16, n0 = nt * 8;
            int ktlo = max(0, m0 - R1b) >> 4, kthi = min(63, m0 + 15 + R1b) >> 4;
            float hh[4] = {0,0,0,0}, hl[4] = {0,0,0,0}, lh[4] = {0,0,0,0};
            tile3<true>(hh, hl, lh, sm + OKH + 4608, sm + OKL + 4608, 72, m0,
                        sm + OR3, sm + OR3 + 4608, 72, n0, ktlo, kthi, lane);
            #pragma unroll
            for (int cr = 0; cr < 4; cr++) {
                int row = m0 + erow + ((cr & 2) << 2);
                int n = n0 + ecol + (cr & 1);
                int s = n >> 3, c = n & 7;
                float v = hh[cr] + hl[cr] + lh[cr];
                int o = (s * 64 + row) * 40 + c;
                bsplit(sm + OR2 + o, sm + OR2 + 5120 + o, v);
            }
            // zero k-pad cols 8..15 (stale from previous group's G4 output)
            {
                int row = tid >> 1, pl = tid & 1;
                uint4 z = make_uint4(0, 0, 0, 0);
                *(uint4*)(sm + OR2 + pl * 5120 + row * 40 + 8) = z;
            }
        }
        __syncthreads();

        // ---- G3: L1 wmult  leaky(R2.A @ W1 + b1) -> R3.B  M=128 K=16 N=16
        for (int t = warp; t < 16; t += 8) {
            const int mt = t & 7, nt = t >> 3;
            const int m0 = mt * 16, n0 = nt * 8;
            float hh[4] = {0,0,0,0}, hl[4] = {0,0,0,0}, lh[4] = {0,0,0,0};
            tile3<false>(hh, hl, lh, sm + OR2, sm + OR2 + 5120, 40, m0,
                         sm + OW1H, sm + OW1L, 16, n0, 0, 0, lane);
            #pragma unroll
            for (int cr = 0; cr < 4; cr++) {
                int row = m0 + erow + ((cr & 2) << 2);
                int col = n0 + ecol + (cr & 1);
                float v = lrelu(hh[cr] + hl[cr] + lh[cr] + sBias[8 + col]);
                int s = row >> 6, h = row & 63;
                int o = h * 72 + s * 16 + col;
                bsplit(sm + OR3 + o, sm + OR3 + 4608 + o, v);
            }
        }
        __syncthreads();

        // ---- G4: L2 mix  K2 @ R3 -> R2.A  M=64 N=32 (banded)
        for (int t = warp; t < 16; t += 8) {
            const int mt = t & 3, nt = t >> 2;
            const int m0 = mt * 16, n0 = nt * 8;
            int ktlo = max(0, m0 - R2b) >> 4, kthi = min(63, m0 + 15 + R2b) >> 4;
            float hh[4] = {0,0,0,0}, hl[4] = {0,0,0,0}, lh[4] = {0,0,0,0};
            tile3<true>(hh, hl, lh, sm + OKH + 2 * 4608, sm + OKL + 2 * 4608, 72, m0,
                        sm + OR3, sm + OR3 + 4608, 72, n0, ktlo, kthi, lane);
            #pragma unroll
            for (int cr = 0; cr < 4; cr++) {
                int row = m0 + erow + ((cr & 2) << 2);
                int n = n0 + ecol + (cr & 1);
                int s = n >> 4, c = n & 15;
                float v = hh[cr] + hl[cr] + lh[cr];
                int o = (s * 64 + row) * 40 + c;
                bsplit(sm + OR2 + o, sm + OR2 + 5120 + o, v);
            }
        }
        __syncthreads();

        // ---- G5: L2 wmult  leaky(R2.A @ W2 + b2) -> R3.B  M=128 K=16 N=32
        for (int t = warp; t < 32; t += 8) {
            const int mt = t & 7, nt = t >> 3;
            const int m0 = mt * 16, n0 = nt * 8;
            float hh[4] = {0,0,0,0}, hl[4] = {0,0,0,0}, lh[4] = {0,0,0,0};
            tile3<false>(hh, hl, lh, sm + OR2, sm + OR2 + 5120, 40, m0,
                         sm + OW2H, sm + OW2L, 16, n0, 0, 0, lane);
            #pragma unroll
            for (int cr = 0; cr < 4; cr++) {
                int row = m0 + erow + ((cr & 2) << 2);
                int col = n0 + ecol + (cr & 1);
                float v = lrelu(hh[cr] + hl[cr] + lh[cr] + sBias[24 + col]);
                int s = row >> 6, h = row & 63;
                int o = h * 72 + s * 32 + col;
                bsplit(sm + OR3 + o, sm + OR3 + 4608 + o, v);
            }
        }
        __syncthreads();

        // ---- G6: L3 mix  K3 @ R3 -> R1.A [s*64+h][c] (stride 72)  M=64 N=64
        for (int t = warp; t < 32; t += 8) {
            const int mt = t & 3, nt = t >> 2;
            const int m0 = mt * 16, n0 = nt * 8;
            int ktlo = max(0, m0 - R3b) >> 4, kthi = min(63, m0 + 15 + R3b) >> 4;
            float hh[4] = {0,0,0,0}, hl[4] = {0,0,0,0}, lh[4] = {0,0,0,0};
            tile3<true>(hh, hl, lh, sm + OKH + 3 * 4608, sm + OKL + 3 * 4608, 72, m0,
                        sm + OR3, sm + OR3 + 4608, 72, n0, ktlo, kthi, lane);
            #pragma unroll
            for (int cr = 0; cr < 4; cr++) {
                int row = m0 + erow + ((cr & 2) << 2);
                int n = n0 + ecol + (cr & 1);
                int s = n >> 5, c = n & 31;
                float v = hh[cr] + hl[cr] + lh[cr];
                int o = (s * 64 + row) * 72 + c;
                bsplit(sm + OR1H + o, sm + OR1L + o, v);
            }
        }
        __syncthreads();

        // ---- G7: L3 wmult  leaky(R1.A @ W3 + b3) -> hi plane R2, lo plane R3
        for (int t = warp; t < 64; t += 8) {
            const int mt = t & 7, nt = t >> 3;
            const int m0 = mt * 16, n0 = nt * 8;
            float hh[4] = {0,0,0,0}, hl[4] = {0,0,0,0}, lh[4] = {0,0,0,0};
            tile3<false>(hh, hl, lh, sm + OR1H, sm + OR1L, 72, m0,
                         sm + OW3H, sm + OW3L, 40, n0, 0, 1, lane);
            #pragma unroll
            for (int cr = 0; cr < 4; cr++) {
                int row = m0 + erow + ((cr & 2) << 2);
                int col = n0 + ecol + (cr & 1);
                float v = lrelu(hh[cr] + hl[cr] + lh[cr] + sBias[56 + col]);
                bsplit(sm + OR2 + row * 72 + col, sm + OR3 + row * 72 + col, v);
            }
        }
        __syncthreads();

        // ---- copy out planes -> g_hHi/g_hLo [b][h*64+c] (16B stores) ----
        for (int idx = tid; idx < 1024; idx += 256) {
            int row = idx >> 3, ch = idx & 7;
            int s = row >> 6, h = row & 63;
            size_t go = (size_t)(gb + s) * 4096 + h * 64 + ch * 8;
            *(uint4*)(g_hHi + go) = *(const uint4*)(sm + OR2 + row * 72 + ch * 8);
            *(uint4*)(g_hLo + go) = *(const uint4*)(sm + OR3 + row * 72 + ch * 8);
        }
        __syncthreads();
    }
}

// ---------------------------------------------------------------------------
// Kernel C: tensor-core compress MLP (unchanged from round 4).
// ---------------------------------------------------------------------------
#define KC_STAGE_H   29952
#define KC_SA_H      0
#define KC_SA_L      9216
#define KC_SW_H      18432
#define KC_SW_L      24192
#define KC_F32_OFF   119808
#define KC_SMEM_BYTES (119808 + 21056)

__device__ __forceinline__ void kc_cpasync16(bf16* dst, const bf16* src) {
    unsigned d = (unsigned)__cvta_generic_to_shared(dst);
    asm volatile("cp.async.cg.shared.global [%0], [%1], 16;" :: "r"(d), "l"(src));
}

__global__ __launch_bounds__(256) void kernC(const float* __restrict__ bm0,
                                             const float* __restrict__ wm1,
                                             const float* __restrict__ bm1,
                                             float* __restrict__ out)
{
    extern __shared__ __align__(16) char smc[];
    bf16* sh = (bf16*)smc;
    float* fpers = (float*)(smc + KC_F32_OFF);
    float* sWm1t = fpers;            // [80][64]
    float* sBm0  = fpers + 5120;
    float* sBm1  = fpers + 5200;
    float* sOut1 = (float*)smc;      // [128][84] after k-loop

    const int tid  = threadIdx.x;
    const int lane = tid & 31;
    const int warp = tid >> 5;
    const int wm = warp >> 1, wn = warp & 1;
    const int m0 = blockIdx.x * 128;

    for (int idx = tid; idx < 4800; idx += 256) {
        int o = idx / 80, c = idx % 80;
        sWm1t[c * 64 + o] = wm1[idx];
    }
    if (tid < 80) sBm0[tid] = bm0[tid];
    if (tid < 60) sBm1[tid] = bm1[tid];

    auto load_stage = [&](int kb, int st) {
        bf16* base = sh + st * KC_STAGE_H;
        const size_t kcol = (size_t)kb * 64;
        #pragma unroll
        for (int c = tid; c < 1024; c += 256) {
            int r = c >> 3, o = c & 7;
            kc_cpasync16(base + KC_SA_H + r * 72 + o * 8,
                         g_hHi + (size_t)(m0 + r) * 4096 + kcol + o * 8);
        }
        #pragma unroll
        for (int c = tid; c < 1024; c += 256) {
            int r = c >> 3, o = c & 7;
            kc_cpasync16(base + KC_SA_L + r * 72 + o * 8,
                         g_hLo + (size_t)(m0 + r) * 4096 + kcol + o * 8);
        }
        for (int c = tid; c < 640; c += 256) {
            int r = c >> 3, o = c & 7;
            kc_cpasync16(base + KC_SW_H + r * 72 + o * 8,
                         g_wHi + (size_t)r * 4096 + kcol + o * 8);
        }
        for (int c = tid; c < 640; c += 256) {
            int r = c >> 3, o = c & 7;
            kc_cpasync16(base + KC_SW_L + r * 72 + o * 8,
                         g_wLo + (size_t)r * 4096 + kcol + o * 8);
        }
    };

    float acc[2][5][4];
    #pragma unroll
    for (int i = 0; i < 2; i++)
        #pragma unroll
        for (int j = 0; j < 5; j++)
            #pragma unroll
            for (int k = 0; k < 4; k++) acc[i][j][k] = 0.f;

    load_stage(0, 0);
    asm volatile("cp.async.commit_group;");

    const int aq  = lane >> 3;
    const int arn = lane & 7;
    const int a_row_off = (aq & 1) * 8 + arn;
    const int a_col_off = (aq >> 1) * 8;
    const int bl  = lane & 15;
    const int b_rn = bl & 7;
    const int b_hi8 = (bl >> 3) * 8;

    const int NK = 64;
    for (int kb = 0; kb < NK; kb++) {
        if (kb + 1 < NK) {
            load_stage(kb + 1, (kb + 1) & 1);
            asm volatile("cp.async.commit_group;");
            asm volatile("cp.async.wait_group 1;");
        } else {
            asm volatile("cp.async.wait_group 0;");
        }
        __syncthreads();

        bf16* base = sh + (kb & 1) * KC_STAGE_H;
        bf16* sAh = base + KC_SA_H;
        bf16* sAl = base + KC_SA_L;
        bf16* sWh = base + KC_SW_H;
        bf16* sWl = base + KC_SW_L;

        #pragma unroll
        for (int sub = 0; sub < 4; sub++) {
            const int kc = sub * 16;
            unsigned bh[5][2], blo[5][2];
            #pragma unroll
            for (int n = 0; n < 5; n++) {
                const int brow = wn * 40 + n * 8 + b_rn;
                ldx2(bh[n],  sWh + brow * 72 + kc + b_hi8);
                ldx2(blo[n], sWl + brow * 72 + kc + b_hi8);
            }
            #pragma unroll
            for (int tmt = 0; tmt < 2; tmt++) {
                const int arow = wm * 32 + tmt * 16 + a_row_off;
                unsigned ah[4], al[4];
                ldx4(ah, sAh + arow * 72 + kc + a_col_off);
                ldx4(al, sAl + arow * 72 + kc + a_col_off);
                #pragma unroll
                for (int n = 0; n < 5; n++) {
                    hmma(acc[tmt][n], ah, bh[n]);
                    hmma(acc[tmt][n], ah, blo[n]);
                    hmma(acc[tmt][n], al, bh[n]);
                }
            }
        }
        __syncthreads();
    }

    #pragma unroll
    for (int tmt = 0; tmt < 2; tmt++)
        #pragma unroll
        for (int n = 0; n < 5; n++)
            #pragma unroll
            for (int cr = 0; cr < 4; cr++) {
                int row = wm * 32 + tmt * 16 + (lane >> 2) + ((cr >= 2) ? 8 : 0);
                int col = wn * 40 + n * 8 + (lane & 3) * 2 + (cr & 1);
                float v = acc[tmt][n][cr] + sBm0[col];
                v = v > 0.f ? v : v * NEG;
                sOut1[row * 84 + col] = v;
            }
    __syncthreads();

    {
        const int tr = tid >> 4;
        const int tc = tid & 15;
        float a2[8][4];
        #pragma unroll
        for (int i = 0; i < 8; i++)
            #pragma unroll
            for (int j = 0; j < 4; j++) a2[i][j] = 0.f;
        for (int c = 0; c < 80; c++) {
            float wv[4];
            #pragma unroll
            for (int j = 0; j < 4; j++) {
                int o = tc * 4 + j;
                wv[j] = (o < 60) ? sWm1t[c * 64 + o] : 0.f;
            }
            #pragma unroll
            for (int i = 0; i < 8; i++) {
                float cv = sOut1[(tr + 16 * i) * 84 + c];
                #pragma unroll
                for (int j = 0; j < 4; j++)
                    a2[i][j] = fmaf(cv, wv[j], a2[i][j]);
            }
        }
        #pragma unroll
        for (int i = 0; i < 8; i++)
            #pragma unroll
            for (int j = 0; j < 4; j++) {
                int o = tc * 4 + j;
                if (o < 60) {
                    float v = a2[i][j] + sBm1[o];
                    v = v > 0.f ? v : v * NEG;
                    out[(size_t)(m0 + tr + 16 * i) * 60 + o] = v;
                }
            }
    }
}

// ---------------------------------------------------------------------------
extern "C" void kernel_launch(void* const* d_in, const int* in_sizes, int n_in,
                              void* d_out, int out_size) {
    (void)in_sizes; (void)n_in; (void)out_size;
    const float* x   = (const float*)d_in[0];
    const float* w0  = (const float*)d_in[1];
    const float* b0  = (const float*)d_in[2];
    const float* s0  = (const float*)d_in[3];
    const float* w1  = (const float*)d_in[4];
    const float* b1  = (const float*)d_in[5];
    const float* s1  = (const float*)d_in[6];
    const float* w2  = (const float*)d_in[7];
    const float* b2  = (const float*)d_in[8];
    const float* s2  = (const float*)d_in[9];
    const float* w3  = (const float*)d_in[10];
    const float* b3  = (const float*)d_in[11];
    const float* s3  = (const float*)d_in[12];
    const float* wm0 = (const float*)d_in[13];
    const float* bm0 = (const float*)d_in[14];
    const float* wm1 = (const float*)d_in[15];
    const float* bm1 = (const float*)d_in[16];
    float* out = (float*)d_out;

    static int attr_done = 0;
    if (!attr_done) {
        cudaFuncSetAttribute(kernG, cudaFuncAttributeMaxDynamicSharedMemorySize, KG_SMEM_BYTES);
        cudaFuncSetAttribute(kernC, cudaFuncAttributeMaxDynamicSharedMemorySize, KC_SMEM_BYTES);
        attr_done = 1;
    }

    kernK<<<1, 256>>>(s0, s1, s2, s3);
    kernT<<<1280, 256>>>(wm0);
    kernG<<<1024, 256, KG_SMEM_BYTES>>>(x, w0, b0, w1, b1, w2, b2, w3, b3);
    kernC<<<128, 256, KC_SMEM_BYTES>>>(bm0, wm1, bm1, out);
}

// round 6
// speedup vs baseline: 1.1054x; 1.0007x over previous
#include <cuda_runtime.h>
#include <cuda_bf16.h>
#include <math.h>

#define NEG 0.01f
typedef __nv_bfloat16 bf16;

// ---------------------------------------------------------------------------
// Scratch (allocation-free rule: __device__ globals)
// ---------------------------------------------------------------------------
__device__ __align__(16) float g_K[4 * 64 * 64];      // 4 normalized gaussian kernels
__device__ int g_band[4];                             // band radius per layer
__device__ __align__(16) bf16 g_wHi[80 * 4096];       // wm0 split hi [o][k]
__device__ __align__(16) bf16 g_wLo[80 * 4096];       // wm0 split lo
__device__ __align__(16) bf16 g_hHi[(size_t)16384 * 4096]; // H split hi [b][k]
__device__ __align__(16) bf16 g_hLo[(size_t)16384 * 4096]; // H split lo

// ---------------------------------------------------------------------------
// Kernel K: build 4 L1-normalized gaussian mixing matrices + band radii
// ---------------------------------------------------------------------------
__global__ void kernK(const float* __restrict__ s0, const float* __restrict__ s1,
                      const float* __restrict__ s2, const float* __restrict__ s3) {
    int t = threadIdx.x;              // 256 threads = 4 layers * 64 rows
    int l = t >> 6, i = t & 63;
    float sg = (l == 0) ? s0[0] : (l == 1) ? s1[0] : (l == 2) ? s2[0] : s3[0];
    float denom = 2.0f * sg * sg;
    float sum = 0.0f;
    for (int j = 0; j < 64; j++) {
        float d = (float)(i - j);
        sum += expf(-(d * d) / denom);
    }
    sum = fmaxf(sum, 1e-12f);
    for (int j = 0; j < 64; j++) {
        float d = (float)(i - j);
        g_K[(l * 64 + i) * 64 + j] = expf(-(d * d) / denom) / sum;
    }
    if (i == 0) {
        float rr = sqrtf(fmaxf(denom, 0.0f) * 18.5f);
        int R = (int)rr + 1;
        if (R > 63) R = 63;
        g_band[l] = R;
    }
}

// ---------------------------------------------------------------------------
// Kernel T: split wm0 [80][4096] fp32 -> bf16 hi/lo (same layout)
// ---------------------------------------------------------------------------
__global__ void kernT(const float* __restrict__ wm0) {
    int idx = blockIdx.x * blockDim.x + threadIdx.x;
    if (idx >= 80 * 4096) return;
    float v = wm0[idx];
    bf16 hi = __float2bfloat16_rn(v);
    bf16 lo = __float2bfloat16_rn(v - __bfloat162float(hi));
    g_wHi[idx] = hi;
    g_wLo[idx] = lo;
}

// ---------------------------------------------------------------------------
// mma helpers
// ---------------------------------------------------------------------------
__device__ __forceinline__ void ldx4(unsigned r[4], const bf16* p) {
    unsigned a = (unsigned)__cvta_generic_to_shared(p);
    asm volatile("ldmatrix.sync.aligned.m8n8.x4.shared.b16 {%0,%1,%2,%3}, [%4];"
                 : "=r"(r[0]), "=r"(r[1]), "=r"(r[2]), "=r"(r[3]) : "r"(a));
}
__device__ __forceinline__ void ldx2(unsigned r[2], const bf16* p) {
    unsigned a = (unsigned)__cvta_generic_to_shared(p);
    asm volatile("ldmatrix.sync.aligned.m8n8.x2.shared.b16 {%0,%1}, [%2];"
                 : "=r"(r[0]), "=r"(r[1]) : "r"(a));
}
__device__ __forceinline__ void ldx2t(unsigned r[2], const bf16* p) {
    unsigned a = (unsigned)__cvta_generic_to_shared(p);
    asm volatile("ldmatrix.sync.aligned.m8n8.x2.trans.shared.b16 {%0,%1}, [%2];"
                 : "=r"(r[0]), "=r"(r[1]) : "r"(a));
}
__device__ __forceinline__ void hmma(float c[4], const unsigned a[4], const unsigned b[2]) {
    asm volatile("mma.sync.aligned.m16n8k16.row.col.f32.bf16.bf16.f32 "
                 "{%0,%1,%2,%3}, {%4,%5,%6,%7}, {%8,%9}, {%0,%1,%2,%3};"
                 : "+f"(c[0]), "+f"(c[1]), "+f"(c[2]), "+f"(c[3])
                 : "r"(a[0]), "r"(a[1]), "r"(a[2]), "r"(a[3]), "r"(b[0]), "r"(b[1]));
}
__device__ __forceinline__ float lrelu(float v) { return v > 0.f ? v : v * NEG; }
__device__ __forceinline__ void bsplit(bf16* hp, bf16* lp, float v) {
    bf16 h = __float2bfloat16_rn(v);
    *hp = h;
    *lp = __float2bfloat16_rn(v - __bfloat162float(h));
}

// Accumulate one 16x8 tile over k-tiles [ktlo..kthi] with 3-term split:
// hh += Ah*Bh, hl += Ah*Bl, lh += Al*Bh. BT: B stored [K][N] (use trans).
template <bool BT>
__device__ __forceinline__ void tile3(float hh[4], float hl[4], float lh[4],
                                      const bf16* Ah, const bf16* Al, int lda, int m0,
                                      const bf16* Bh, const bf16* Bl, int ldb, int n0,
                                      int ktlo, int kthi, int lane) {
    const int arow = m0 + (lane & 7) + ((lane >> 3) & 1) * 8;
    const int acol = (lane >> 4) * 8;
    for (int kt = ktlo; kt <= kthi; kt++) {
        const int kc = kt * 16;
        unsigned a0[4], a1[4], b0[2], b1[2];
        ldx4(a0, Ah + arow * lda + kc + acol);
        ldx4(a1, Al + arow * lda + kc + acol);
        if (BT) {
            const int br = kc + (lane & 15);
            ldx2t(b0, Bh + br * ldb + n0);
            ldx2t(b1, Bl + br * ldb + n0);
        } else {
            const int br = n0 + (lane & 7);
            const int bc = kc + ((lane >> 3) & 1) * 8;
            ldx2(b0, Bh + br * ldb + bc);
            ldx2(b1, Bl + br * ldb + bc);
        }
        hmma(hh, a0, b0);
        hmma(hl, a0, b1);
        hmma(lh, a1, b0);
    }
}

// ---------------------------------------------------------------------------
// Kernel G (tensor-core): fused 4-layer gaussian stack.
// 256 threads / 8 warps per block; block processes 16 samples as 8 groups
// of S=2. Reordered algebra (rows of K sum to 1): layer0 = leaky(K0@(xW0+b0)),
// layers 1..3 = leaky((Kl@T)Wl + bl). All ops are split-bf16 mma.
//
// SMEM (halves): K hi/lo 4x[64][72] | R1 A-layout [128][72] hi/lo (X, L3m out)
// | R2, R3: 10240-half regions (B-layout 64x72 hi/lo, or A-layout 128x40
// hi/lo, or one out plane 128x72) | weights hi/lo | fp32 biases.
// ---------------------------------------------------------------------------
#define OKH   0
#define OKL   18432
#define OR1H  36864
#define OR1L  46080
#define OR2   55296
#define OR3   65536
#define OW0H  75776
#define OW0L  76352
#define OW1H  76928
#define OW1L  77184
#define OW2H  77440
#define OW2L  77952
#define OW3H  78464
#define OW3L  81024
#define OHALVES 83584
#define KG_SMEM_BYTES (OHALVES * 2 + 480)
// R2/R3 sub-offsets: B-layout hi +0 / lo +4608 ; A-layout hi +0 / lo +5120

__global__ __launch_bounds__(256) void kernG(
    const float* __restrict__ x,
    const float* __restrict__ w0, const float* __restrict__ b0,
    const float* __restrict__ w1, const float* __restrict__ b1,
    const float* __restrict__ w2, const float* __restrict__ b2,
    const float* __restrict__ w3, const float* __restrict__ b3)
{
    extern __shared__ __align__(16) bf16 sm[];
    float* sBias = (float*)(sm + OHALVES);   // b0@0, b1@8, b2@24, b3@56

    const int tid = threadIdx.x;
    const int lane = tid & 31;
    const int warp = tid >> 5;
    const int R0 = g_band[0], R1b = g_band[1], R2b = g_band[2], R3b = g_band[3];

    // ---- one-time staging ----
    for (int idx = tid; idx < 16384; idx += 256) {
        int l = idx >> 12, i = (idx >> 6) & 63, j = idx & 63;
        bsplit(sm + OKH + l * 4608 + i * 72 + j, sm + OKL + l * 4608 + i * 72 + j, g_K[idx]);
    }
    for (int idx = tid; idx < 512; idx += 256) {    // w0 [8][64] -> [8][72]
        int o = idx >> 6, c = idx & 63;
        bsplit(sm + OW0H + o * 72 + c, sm + OW0L + o * 72 + c, w0[idx]);
    }
    if (tid < 256) {                                // w1 [16][8] -> [16][16] k-padded
        int o = tid >> 4, c = tid & 15;
        float v = (c < 8) ? w1[o * 8 + c] : 0.f;
        bsplit(sm + OW1H + o * 16 + c, sm + OW1L + o * 16 + c, v);
    }
    for (int idx = tid; idx < 512; idx += 256) {    // w2 [32][16]
        int o = idx >> 4, c = idx & 15;
        bsplit(sm + OW2H + o * 16 + c, sm + OW2L + o * 16 + c, w2[idx]);
    }
    for (int idx = tid; idx < 2048; idx += 256) {   // w3 [64][32] -> [64][40]
        int o = idx >> 5, c = idx & 31;
        bsplit(sm + OW3H + o * 40 + c, sm + OW3L + o * 40 + c, w3[idx]);
    }
    if (tid < 8) sBias[tid] = b0[tid];
    else if (tid >= 32 && tid < 48) sBias[8 + tid - 32] = b1[tid - 32];
    else if (tid >= 64 && tid < 96) sBias[24 + tid - 64] = b2[tid - 64];
    else if (tid >= 128 && tid < 192) sBias[56 + tid - 128] = b3[tid - 128];
    __syncthreads();

    const int erow = lane >> 2;           // epilogue base row
    const int ecol = (lane & 3) * 2;      // epilogue base col

    for (int g = 0; g < 8; g++) {
        const int gb = blockIdx.x * 16 + g * 2;

        // ---- X load + split -> R1 (A-layout [s*64+h][72]) ----
        {
            const float4* xb = (const float4*)x;
            for (int idx = tid; idx < 2048; idx += 256) {
                int s = idx >> 10, rem = idx & 1023;
                int h = rem >> 4, c4 = rem & 15;
                float4 v = xb[(size_t)(gb + s) * 1024 + rem];
                bf16* hp = sm + OR1H + (s * 64 + h) * 72 + c4 * 4;
                bf16* lp = sm + OR1L + (s * 64 + h) * 72 + c4 * 4;
                bsplit(hp + 0, lp + 0, v.x); bsplit(hp + 1, lp + 1, v.y);
                bsplit(hp + 2, lp + 2, v.z); bsplit(hp + 3, lp + 3, v.w);
            }
        }
        __syncthreads();

        // ---- G0: L0 wmult  M=128 K=64 N=8 : X@W0 + b0 -> R2.B [h][s*8+c]
        {
            const int m0 = warp * 16;
            float hh[4] = {0,0,0,0}, hl[4] = {0,0,0,0}, lh[4] = {0,0,0,0};
            tile3<false>(hh, hl, lh, sm + OR1H, sm + OR1L, 72, m0,
                         sm + OW0H, sm + OW0L, 72, 0, 0, 3, lane);
            #pragma unroll
            for (int cr = 0; cr < 4; cr++) {
                int row = m0 + erow + ((cr & 2) << 2);
                int col = ecol + (cr & 1);
                float v = hh[cr] + hl[cr] + lh[cr] + sBias[col];
                int s = row >> 6, h = row & 63;
                int o = h * 72 + s * 8 + col;
                bsplit(sm + OR2 + o, sm + OR2 + 4608 + o, v);
            }
        }
        __syncthreads();

        // ---- G1: L0 mix  leaky(K0 @ R2) -> R3.B   M=64 N=16 (banded)
        {
            const int mt = warp >> 1, nt = warp & 1;
            const int m0 = mt * 16, n0 = nt * 8;
            int ktlo = max(0, m0 - R0) >> 4, kthi = min(63, m0 + 15 + R0) >> 4;
            float hh[4] = {0,0,0,0}, hl[4] = {0,0,0,0}, lh[4] = {0,0,0,0};
            tile3<true>(hh, hl, lh, sm + OKH, sm + OKL, 72, m0,
                        sm + OR2, sm + OR2 + 4608, 72, n0, ktlo, kthi, lane);
            #pragma unroll
            for (int cr = 0; cr < 4; cr++) {
                int row = m0 + erow + ((cr & 2) << 2);
                int n = n0 + ecol + (cr & 1);
                float v = lrelu(hh[cr] + hl[cr] + lh[cr]);
                bsplit(sm + OR3 + row * 72 + n, sm + OR3 + 4608 + row * 72 + n, v);
            }
        }
        __syncthreads();

        // ---- G2: L1 mix  K1 @ R3 -> R2.A [s*64+h][c] (+zero pad c8..15)
        {
            const int mt = warp >> 1, nt = warp & 1;
            const int m0 = mt * 16, n0 = nt * 8;
            int ktlo = max(0, m0 - R1b) >> 4, kthi = min(63, m0 + 15 + R1b) >> 4;
            float hh[4] = {0,0,0,0}, hl[4] = {0,0,0,0}, lh[4] = {0,0,0,0};
            tile3<true>(hh, hl, lh, sm + OKH + 4608, sm + OKL + 4608, 72, m0,
                        sm + OR3, sm + OR3 + 4608, 72, n0, ktlo, kthi, lane);
            #pragma unroll
            for (int cr = 0; cr < 4; cr++) {
                int row = m0 + erow + ((cr & 2) << 2);
                int n = n0 + ecol + (cr & 1);
                int s = n >> 3, c = n & 7;
                float v = hh[cr] + hl[cr] + lh[cr];
                int o = (s * 64 + row) * 40 + c;
                bsplit(sm + OR2 + o, sm + OR2 + 5120 + o, v);
            }
            // zero k-pad cols 8..15 (stale from previous group's G4 output)
            {
                int row = tid >> 1, pl = tid & 1;
                uint4 z = make_uint4(0, 0, 0, 0);
                *(uint4*)(sm + OR2 + pl * 5120 + row * 40 + 8) = z;
            }
        }
        __syncthreads();

        // ---- G3: L1 wmult  leaky(R2.A @ W1 + b1) -> R3.B  M=128 K=16 N=16
        for (int t = warp; t < 16; t += 8) {
            const int mt = t & 7, nt = t >> 3;
            const int m0 = mt * 16, n0 = nt * 8;
            float hh[4] = {0,0,0,0}, hl[4] = {0,0,0,0}, lh[4] = {0,0,0,0};
            tile3<false>(hh, hl, lh, sm + OR2, sm + OR2 + 5120, 40, m0,
                         sm + OW1H, sm + OW1L, 16, n0, 0, 0, lane);
            #pragma unroll
            for (int cr = 0; cr < 4; cr++) {
                int row = m0 + erow + ((cr & 2) << 2);
                int col = n0 + ecol + (cr & 1);
                float v = lrelu(hh[cr] + hl[cr] + lh[cr] + sBias[8 + col]);
                int s = row >> 6, h = row & 63;
                int o = h * 72 + s * 16 + col;
                bsplit(sm + OR3 + o, sm + OR3 + 4608 + o, v);
            }
        }
        __syncthreads();

        // ---- G4: L2 mix  K2 @ R3 -> R2.A  M=64 N=32 (banded)
        for (int t = warp; t < 16; t += 8) {
            const int mt = t & 3, nt = t >> 2;
            const int m0 = mt * 16, n0 = nt * 8;
            int ktlo = max(0, m0 - R2b) >> 4, kthi = min(63, m0 + 15 + R2b) >> 4;
            float hh[4] = {0,0,0,0}, hl[4] = {0,0,0,0}, lh[4] = {0,0,0,0};
            tile3<true>(hh, hl, lh, sm + OKH + 2 * 4608, sm + OKL + 2 * 4608, 72, m0,
                        sm + OR3, sm + OR3 + 4608, 72, n0, ktlo, kthi, lane);
            #pragma unroll
            for (int cr = 0; cr < 4; cr++) {
                int row = m0 + erow + ((cr & 2) << 2);
                int n = n0 + ecol + (cr & 1);
                int s = n >> 4, c = n & 15;
                float v = hh[cr] + hl[cr] + lh[cr];
                int o = (s * 64 + row) * 40 + c;
                bsplit(sm + OR2 + o, sm + OR2 + 5120 + o, v);
            }
        }
        __syncthreads();

        // ---- G5: L2 wmult  leaky(R2.A @ W2 + b2) -> R3.B  M=128 K=16 N=32
        for (int t = warp; t < 32; t += 8) {
            const int mt = t & 7, nt = t >> 3;
            const int m0 = mt * 16, n0 = nt * 8;
            float hh[4] = {0,0,0,0}, hl[4] = {0,0,0,0}, lh[4] = {0,0,0,0};
            tile3<false>(hh, hl, lh, sm + OR2, sm + OR2 + 5120, 40, m0,
                         sm + OW2H, sm + OW2L, 16, n0, 0, 0, lane);
            #pragma unroll
            for (int cr = 0; cr < 4; cr++) {
                int row = m0 + erow + ((cr & 2) << 2);
                int col = n0 + ecol + (cr & 1);
                float v = lrelu(hh[cr] + hl[cr] + lh[cr] + sBias[24 + col]);
                int s = row >> 6, h = row & 63;
                int o = h * 72 + s * 32 + col;
                bsplit(sm + OR3 + o, sm + OR3 + 4608 + o, v);
            }
        }
        __syncthreads();

        // ---- G6: L3 mix  K3 @ R3 -> R1.A [s*64+h][c] (stride 72)  M=64 N=64
        for (int t = warp; t < 32; t += 8) {
            const int mt = t & 3, nt = t >> 2;
            const int m0 = mt * 16, n0 = nt * 8;
            int ktlo = max(0, m0 - R3b) >> 4, kthi = min(63, m0 + 15 + R3b) >> 4;
            float hh[4] = {0,0,0,0}, hl[4] = {0,0,0,0}, lh[4] = {0,0,0,0};
            tile3<true>(hh, hl, lh, sm + OKH + 3 * 4608, sm + OKL + 3 * 4608, 72, m0,
                        sm + OR3, sm + OR3 + 4608, 72, n0, ktlo, kthi, lane);
            #pragma unroll
            for (int cr = 0; cr < 4; cr++) {
                int row = m0 + erow + ((cr & 2) << 2);
                int n = n0 + ecol + (cr & 1);
                int s = n >> 5, c = n & 31;
                float v = hh[cr] + hl[cr] + lh[cr];
                int o = (s * 64 + row) * 72 + c;
                bsplit(sm + OR1H + o, sm + OR1L + o, v);
            }
        }
        __syncthreads();

        // ---- G7: L3 wmult  leaky(R1.A @ W3 + b3) -> hi plane R2, lo plane R3
        for (int t = warp; t < 64; t += 8) {
            const int mt = t & 7, nt = t >> 3;
            const int m0 = mt * 16, n0 = nt * 8;
            float hh[4] = {0,0,0,0}, hl[4] = {0,0,0,0}, lh[4] = {0,0,0,0};
            tile3<false>(hh, hl, lh, sm + OR1H, sm + OR1L, 72, m0,
                         sm + OW3H, sm + OW3L, 40, n0, 0, 1, lane);
            #pragma unroll
            for (int cr = 0; cr < 4; cr++) {
                int row = m0 + erow + ((cr & 2) << 2);
                int col = n0 + ecol + (cr & 1);
                float v = lrelu(hh[cr] + hl[cr] + lh[cr] + sBias[56 + col]);
                bsplit(sm + OR2 + row * 72 + col, sm + OR3 + row * 72 + col, v);
            }
        }
        __syncthreads();

        // ---- copy out planes -> g_hHi/g_hLo [b][h*64+c] (16B stores) ----
        for (int idx = tid; idx < 1024; idx += 256) {
            int row = idx >> 3, ch = idx & 7;
            int s = row >> 6, h = row & 63;
            size_t go = (size_t)(gb + s) * 4096 + h * 64 + ch * 8;
            *(uint4*)(g_hHi + go) = *(const uint4*)(sm + OR2 + row * 72 + ch * 8);
            *(uint4*)(g_hLo + go) = *(const uint4*)(sm + OR3 + row * 72 + ch * 8);
        }
        __syncthreads();
    }
}

// ---------------------------------------------------------------------------
// Kernel C: tensor-core compress MLP (unchanged from round 4).
// ---------------------------------------------------------------------------
#define KC_STAGE_H   29952
#define KC_SA_H      0
#define KC_SA_L      9216
#define KC_SW_H      18432
#define KC_SW_L      24192
#define KC_F32_OFF   119808
#define KC_SMEM_BYTES (119808 + 21056)

__device__ __forceinline__ void kc_cpasync16(bf16* dst, const bf16* src) {
    unsigned d = (unsigned)__cvta_generic_to_shared(dst);
    asm volatile("cp.async.cg.shared.global [%0], [%1], 16;" :: "r"(d), "l"(src));
}

__global__ __launch_bounds__(256) void kernC(const float* __restrict__ bm0,
                                             const float* __restrict__ wm1,
                                             const float* __restrict__ bm1,
                                             float* __restrict__ out)
{
    extern __shared__ __align__(16) char smc[];
    bf16* sh = (bf16*)smc;
    float* fpers = (float*)(smc + KC_F32_OFF);
    float* sWm1t = fpers;            // [80][64]
    float* sBm0  = fpers + 5120;
    float* sBm1  = fpers + 5200;
    float* sOut1 = (float*)smc;      // [128][84] after k-loop

    const int tid  = threadIdx.x;
    const int lane = tid & 31;
    const int warp = tid >> 5;
    const int wm = warp >> 1, wn = warp & 1;
    const int m0 = blockIdx.x * 128;

    for (int idx = tid; idx < 4800; idx += 256) {
        int o = idx / 80, c = idx % 80;
        sWm1t[c * 64 + o] = wm1[idx];
    }
    if (tid < 80) sBm0[tid] = bm0[tid];
    if (tid < 60) sBm1[tid] = bm1[tid];

    auto load_stage = [&](int kb, int st) {
        bf16* base = sh + st * KC_STAGE_H;
        const size_t kcol = (size_t)kb * 64;
        #pragma unroll
        for (int c = tid; c < 1024; c += 256) {
            int r = c >> 3, o = c & 7;
            kc_cpasync16(base + KC_SA_H + r * 72 + o * 8,
                         g_hHi + (size_t)(m0 + r) * 4096 + kcol + o * 8);
        }
        #pragma unroll
        for (int c = tid; c < 1024; c += 256) {
            int r = c >> 3, o = c & 7;
            kc_cpasync16(base + KC_SA_L + r * 72 + o * 8,
                         g_hLo + (size_t)(m0 + r) * 4096 + kcol + o * 8);
        }
        for (int c = tid; c < 640; c += 256) {
            int r = c >> 3, o = c & 7;
            kc_cpasync16(base + KC_SW_H + r * 72 + o * 8,
                         g_wHi + (size_t)r * 4096 + kcol + o * 8);
        }
        for (int c = tid; c < 640; c += 256) {
            int r = c >> 3, o = c & 7;
            kc_cpasync16(base + KC_SW_L + r * 72 + o * 8,
                         g_wLo + (size_t)r * 4096 + kcol + o * 8);
        }
    };

    float acc[2][5][4];
    #pragma unroll
    for (int i = 0; i < 2; i++)
        #pragma unroll
        for (int j = 0; j < 5; j++)
            #pragma unroll
            for (int k = 0; k < 4; k++) acc[i][j][k] = 0.f;

    load_stage(0, 0);
    asm volatile("cp.async.commit_group;");

    const int aq  = lane >> 3;
    const int arn = lane & 7;
    const int a_row_off = (aq & 1) * 8 + arn;
    const int a_col_off = (aq >> 1) * 8;
    const int bl  = lane & 15;
    const int b_rn = bl & 7;
    const int b_hi8 = (bl >> 3) * 8;

    const int NK = 64;
    for (int kb = 0; kb < NK; kb++) {
        if (kb + 1 < NK) {
            load_stage(kb + 1, (kb + 1) & 1);
            asm volatile("cp.async.commit_group;");
            asm volatile("cp.async.wait_group 1;");
        } else {
            asm volatile("cp.async.wait_group 0;");
        }
        __syncthreads();

        bf16* base = sh + (kb & 1) * KC_STAGE_H;
        bf16* sAh = base + KC_SA_H;
        bf16* sAl = base + KC_SA_L;
        bf16* sWh = base + KC_SW_H;
        bf16* sWl = base + KC_SW_L;

        #pragma unroll
        for (int sub = 0; sub < 4; sub++) {
            const int kc = sub * 16;
            unsigned bh[5][2], blo[5][2];
            #pragma unroll
            for (int n = 0; n < 5; n++) {
                const int brow = wn * 40 + n * 8 + b_rn;
                ldx2(bh[n],  sWh + brow * 72 + kc + b_hi8);
                ldx2(blo[n], sWl + brow * 72 + kc + b_hi8);
            }
            #pragma unroll
            for (int tmt = 0; tmt < 2; tmt++) {
                const int arow = wm * 32 + tmt * 16 + a_row_off;
                unsigned ah[4], al[4];
                ldx4(ah, sAh + arow * 72 + kc + a_col_off);
                ldx4(al, sAl + arow * 72 + kc + a_col_off);
                #pragma unroll
                for (int n = 0; n < 5; n++) {
                    hmma(acc[tmt][n], ah, bh[n]);
                    hmma(acc[tmt][n], ah, blo[n]);
                    hmma(acc[tmt][n], al, bh[n]);
                }
            }
        }
        __syncthreads();
    }

    #pragma unroll
    for (int tmt = 0; tmt < 2; tmt++)
        #pragma unroll
        for (int n = 0; n < 5; n++)
            #pragma unroll
            for (int cr = 0; cr < 4; cr++) {
                int row = wm * 32 + tmt * 16 + (lane >> 2) + ((cr >= 2) ? 8 : 0);
                int col = wn * 40 + n * 8 + (lane & 3) * 2 + (cr & 1);
                float v = acc[tmt][n][cr] + sBm0[col];
                v = v > 0.f ? v : v * NEG;
                sOut1[row * 84 + col] = v;
            }
    __syncthreads();

    {
        const int tr = tid >> 4;
        const int tc = tid & 15;
        float a2[8][4];
        #pragma unroll
        for (int i = 0; i < 8; i++)
            #pragma unroll
            for (int j = 0; j < 4; j++) a2[i][j] = 0.f;
        for (int c = 0; c < 80; c++) {
            float wv[4];
            #pragma unroll
            for (int j = 0; j < 4; j++) {
                int o = tc * 4 + j;
                wv[j] = (o < 60) ? sWm1t[c * 64 + o] : 0.f;
            }
            #pragma unroll
            for (int i = 0; i < 8; i++) {
                float cv = sOut1[(tr + 16 * i) * 84 + c];
                #pragma unroll
                for (int j = 0; j < 4; j++)
                    a2[i][j] = fmaf(cv, wv[j], a2[i][j]);
            }
        }
        #pragma unroll
        for (int i = 0; i < 8; i++)
            #pragma unroll
            for (int j = 0; j < 4; j++) {
                int o = tc * 4 + j;
                if (o < 60) {
                    float v = a2[i][j] + sBm1[o];
                    v = v > 0.f ? v : v * NEG;
                    out[(size_t)(m0 + tr + 16 * i) * 60 + o] = v;
                }
            }
    }
}

// ---------------------------------------------------------------------------
extern "C" void kernel_launch(void* const* d_in, const int* in_sizes, int n_in,
                              void* d_out, int out_size) {
    (void)in_sizes; (void)n_in; (void)out_size;
    const float* x   = (const float*)d_in[0];
    const float* w0  = (const float*)d_in[1];
    const float* b0  = (const float*)d_in[2];
    const float* s0  = (const float*)d_in[3];
    const float* w1  = (const float*)d_in[4];
    const float* b1  = (const float*)d_in[5];
    const float* s1  = (const float*)d_in[6];
    const float* w2  = (const float*)d_in[7];
    const float* b2  = (const float*)d_in[8];
    const float* s2  = (const float*)d_in[9];
    const float* w3  = (const float*)d_in[10];
    const float* b3  = (const float*)d_in[11];
    const float* s3  = (const float*)d_in[12];
    const float* wm0 = (const float*)d_in[13];
    const float* bm0 = (const float*)d_in[14];
    const float* wm1 = (const float*)d_in[15];
    const float* bm1 = (const float*)d_in[16];
    float* out = (float*)d_out;

    static int attr_done = 0;
    if (!attr_done) {
        cudaFuncSetAttribute(kernG, cudaFuncAttributeMaxDynamicSharedMemorySize, KG_SMEM_BYTES);
        cudaFuncSetAttribute(kernC, cudaFuncAttributeMaxDynamicSharedMemorySize, KC_SMEM_BYTES);
        attr_done = 1;
    }

    kernK<<<1, 256>>>(s0, s1, s2, s3);
    kernT<<<1280, 256>>>(wm0);
    kernG<<<1024, 256, KG_SMEM_BYTES>>>(x, w0, b0, w1, b1, w2, b2, w3, b3);
    kernC<<<128, 256, KC_SMEM_BYTES>>>(bm0, wm1, bm1, out);
}

// round 9
// speedup vs baseline: 1.5987x; 1.4462x over previous
#include <cuda_runtime.h>
#include <cuda_bf16.h>
#include <math.h>

#define NEG 0.01f
typedef __nv_bfloat16 bf16;

// ---------------------------------------------------------------------------
// Scratch (allocation-free rule: __device__ globals)
// ---------------------------------------------------------------------------
__device__ __align__(16) float g_K[4 * 64 * 64];      // 4 normalized gaussian kernels
__device__ int g_band[4];                             // band radius per layer
__device__ __align__(16) bf16 g_wHi[80 * 4096];       // wm0 split hi [o][k]
__device__ __align__(16) bf16 g_wLo[80 * 4096];       // wm0 split lo
__device__ __align__(16) bf16 g_hHi[(size_t)16384 * 4096]; // H split hi [b][k]
__device__ __align__(16) bf16 g_hLo[(size_t)16384 * 4096]; // H split lo

// ---------------------------------------------------------------------------
// Kernel K: build 4 L1-normalized gaussian mixing matrices + band radii
// ---------------------------------------------------------------------------
__global__ void kernK(const float* __restrict__ s0, const float* __restrict__ s1,
                      const float* __restrict__ s2, const float* __restrict__ s3) {
    int t = threadIdx.x;              // 256 threads = 4 layers * 64 rows
    int l = t >> 6, i = t & 63;
    float sg = (l == 0) ? s0[0] : (l == 1) ? s1[0] : (l == 2) ? s2[0] : s3[0];
    float denom = 2.0f * sg * sg;
    float sum = 0.0f;
    for (int j = 0; j < 64; j++) {
        float d = (float)(i - j);
        sum += expf(-(d * d) / denom);
    }
    sum = fmaxf(sum, 1e-12f);
    for (int j = 0; j < 64; j++) {
        float d = (float)(i - j);
        g_K[(l * 64 + i) * 64 + j] = expf(-(d * d) / denom) / sum;
    }
    if (i == 0) {
        float rr = sqrtf(fmaxf(denom, 0.0f) * 18.5f);
        int R = (int)rr + 1;
        if (R > 63) R = 63;
        g_band[l] = R;
    }
}

// ---------------------------------------------------------------------------
// Kernel T: split wm0 [80][4096] fp32 -> bf16 hi/lo (same layout)
// ---------------------------------------------------------------------------
__global__ void kernT(const float* __restrict__ wm0) {
    int idx = blockIdx.x * blockDim.x + threadIdx.x;
    if (idx >= 80 * 4096) return;
    float v = wm0[idx];
    bf16 hi = __float2bfloat16_rn(v);
    bf16 lo = __float2bfloat16_rn(v - __bfloat162float(hi));
    g_wHi[idx] = hi;
    g_wLo[idx] = lo;
}

// ---------------------------------------------------------------------------
// mma helpers
// ---------------------------------------------------------------------------
__device__ __forceinline__ void ldx4(unsigned r[4], const bf16* p) {
    unsigned a = (unsigned)__cvta_generic_to_shared(p);
    asm volatile("ldmatrix.sync.aligned.m8n8.x4.shared.b16 {%0,%1,%2,%3}, [%4];"
                 : "=r"(r[0]), "=r"(r[1]), "=r"(r[2]), "=r"(r[3]) : "r"(a));
}
__device__ __forceinline__ void ldx2(unsigned r[2], const bf16* p) {
    unsigned a = (unsigned)__cvta_generic_to_shared(p);
    asm volatile("ldmatrix.sync.aligned.m8n8.x2.shared.b16 {%0,%1}, [%2];"
                 : "=r"(r[0]), "=r"(r[1]) : "r"(a));
}
__device__ __forceinline__ void ldx2t(unsigned r[2], const bf16* p) {
    unsigned a = (unsigned)__cvta_generic_to_shared(p);
    asm volatile("ldmatrix.sync.aligned.m8n8.x2.trans.shared.b16 {%0,%1}, [%2];"
                 : "=r"(r[0]), "=r"(r[1]) : "r"(a));
}
__device__ __forceinline__ void hmma(float c[4], const unsigned a[4], const unsigned b[2]) {
    asm volatile("mma.sync.aligned.m16n8k16.row.col.f32.bf16.bf16.f32 "
                 "{%0,%1,%2,%3}, {%4,%5,%6,%7}, {%8,%9}, {%0,%1,%2,%3};"
                 : "+f"(c[0]), "+f"(c[1]), "+f"(c[2]), "+f"(c[3])
                 : "r"(a[0]), "r"(a[1]), "r"(a[2]), "r"(a[3]), "r"(b[0]), "r"(b[1]));
}
__device__ __forceinline__ float lrelu(float v) { return v > 0.f ? v : v * NEG; }
__device__ __forceinline__ void bsplit(bf16* hp, bf16* lp, float v) {
    bf16 h = __float2bfloat16_rn(v);
    *hp = h;
    *lp = __float2bfloat16_rn(v - __bfloat162float(h));
}
// packed pair split: hp/lp must be 4B aligned, writes 2 bf16 each
__device__ __forceinline__ void bsplit2(bf16* hp, bf16* lp, float v0, float v1) {
    __nv_bfloat162 h = __floats2bfloat162_rn(v0, v1);
    float r0 = v0 - __bfloat162float(h.x);
    float r1 = v1 - __bfloat162float(h.y);
    __nv_bfloat162 l = __floats2bfloat162_rn(r0, r1);
    *(__nv_bfloat162*)hp = h;
    *(__nv_bfloat162*)lp = l;
}

// Accumulate one 16x8 tile over k-tiles [ktlo..kthi] with 3-term split:
// hh += Ah*Bh, hl += Ah*Bl, lh += Al*Bh. BT: B stored [K][N] (use trans).
template <bool BT>
__device__ __forceinline__ void tile3(float hh[4], float hl[4], float lh[4],
                                      const bf16* Ah, const bf16* Al, int lda, int m0,
                                      const bf16* Bh, const bf16* Bl, int ldb, int n0,
                                      int ktlo, int kthi, int lane) {
    const int arow = m0 + (lane & 7) + ((lane >> 3) & 1) * 8;
    const int acol = (lane >> 4) * 8;
    for (int kt = ktlo; kt <= kthi; kt++) {
        const int kc = kt * 16;
        unsigned a0[4], a1[4], b0[2], b1[2];
        ldx4(a0, Ah + arow * lda + kc + acol);
        ldx4(a1, Al + arow * lda + kc + acol);
        if (BT) {
            const int br = kc + (lane & 15);
            ldx2t(b0, Bh + br * ldb + n0);
            ldx2t(b1, Bl + br * ldb + n0);
        } else {
            const int br = n0 + (lane & 7);
            const int bc = kc + ((lane >> 3) & 1) * 8;
            ldx2(b0, Bh + br * ldb + bc);
            ldx2(b1, Bl + br * ldb + bc);
        }
        hmma(hh, a0, b0);
        hmma(hl, a0, b1);
        hmma(lh, a1, b0);
    }
}

// ---------------------------------------------------------------------------
// Kernel G (tensor-core): fused 4-layer gaussian stack.
// 512 threads / 16 warps per block; block processes 16 samples as 8 groups
// of S=2. Next group's x prefetched into registers during current group.
// Reordered algebra (rows of K sum to 1): layer0 = leaky(K0@(xW0+b0)),
// layers 1..3 = leaky((Kl@T)Wl + bl). All ops split-bf16 mma, fp32 accum.
// ---------------------------------------------------------------------------
#define OKH   0
#define OKL   18432
#define OR1H  36864
#define OR1L  46080
#define OR2   55296
#define OR3   65536
#define OW0H  75776
#define OW0L  76352
#define OW1H  76928
#define OW1L  77184
#define OW2H  77440
#define OW2L  77952
#define OW3H  78464
#define OW3L  81024
#define OHALVES 83584
#define KG_SMEM_BYTES (OHALVES * 2 + 480)
// R2/R3 sub-offsets: B-layout hi +0 / lo +4608 ; A-layout hi +0 / lo +5120

__global__ __launch_bounds__(512) void kernG(
    const float* __restrict__ x,
    const float* __restrict__ w0, const float* __restrict__ b0,
    const float* __restrict__ w1, const float* __restrict__ b1,
    const float* __restrict__ w2, const float* __restrict__ b2,
    const float* __restrict__ w3, const float* __restrict__ b3)
{
    extern __shared__ __align__(16) bf16 sm[];
    float* sBias = (float*)(sm + OHALVES);   // b0@0, b1@8, b2@24, b3@56

    const int tid = threadIdx.x;
    const int lane = tid & 31;
    const int warp = tid >> 5;
    const int R0 = g_band[0], R1b = g_band[1], R2b = g_band[2], R3b = g_band[3];

    const float4* xb4 = (const float4*)x;
    float4 xr[4];
    // prefetch group 0 x while we stage constants
    {
        const int gb = blockIdx.x * 16;
        #pragma unroll
        for (int k = 0; k < 4; k++) {
            int idx = tid + k * 512;
            xr[k] = xb4[(size_t)(gb + (idx >> 10)) * 1024 + (idx & 1023)];
        }
    }

    // ---- one-time staging ----
    for (int idx = tid; idx < 16384; idx += 512) {
        int l = idx >> 12, i = (idx >> 6) & 63, j = idx & 63;
        bsplit(sm + OKH + l * 4608 + i * 72 + j, sm + OKL + l * 4608 + i * 72 + j, g_K[idx]);
    }
    if (tid < 512) {                                // w0 [8][64] -> [8][72]
        int o = tid >> 6, c = tid & 63;
        bsplit(sm + OW0H + o * 72 + c, sm + OW0L + o * 72 + c, w0[tid]);
    }
    if (tid < 256) {                                // w1 [16][8] -> [16][16] k-padded
        int o = tid >> 4, c = tid & 15;
        float v = (c < 8) ? w1[o * 8 + c] : 0.f;
        bsplit(sm + OW1H + o * 16 + c, sm + OW1L + o * 16 + c, v);
    }
    if (tid < 512) {                                // w2 [32][16]
        int o = tid >> 4, c = tid & 15;
        bsplit(sm + OW2H + o * 16 + c, sm + OW2L + o * 16 + c, w2[tid]);
    }
    for (int idx = tid; idx < 2048; idx += 512) {   // w3 [64][32] -> [64][40]
        int o = idx >> 5, c = idx & 31;
        bsplit(sm + OW3H + o * 40 + c, sm + OW3L + o * 40 + c, w3[idx]);
    }
    if (tid < 8) sBias[tid] = b0[tid];
    else if (tid >= 32 && tid < 48) sBias[8 + tid - 32] = b1[tid - 32];
    else if (tid >= 64 && tid < 96) sBias[24 + tid - 64] = b2[tid - 64];
    else if (tid >= 128 && tid < 192) sBias[56 + tid - 128] = b3[tid - 128];
    __syncthreads();

    const int erow = lane >> 2;           // epilogue base row
    const int ecol = (lane & 3) * 2;      // epilogue base col (even)

    for (int g = 0; g < 8; g++) {
        const int gb = blockIdx.x * 16 + g * 2;

        // ---- split prefetched X regs -> R1 (A-layout [s*64+h][72]) ----
        #pragma unroll
        for (int k = 0; k < 4; k++) {
            int idx = tid + k * 512;
            int s = idx >> 10, rem = idx & 1023;
            int h = rem >> 4, c4 = rem & 15;
            int o = (s * 64 + h) * 72 + c4 * 4;
            bsplit2(sm + OR1H + o, sm + OR1L + o, xr[k].x, xr[k].y);
            bsplit2(sm + OR1H + o + 2, sm + OR1L + o + 2, xr[k].z, xr[k].w);
        }
        __syncthreads();

        // prefetch NEXT group's x (consumed only after this group's copy-out)
        if (g < 7) {
            const int gbn = gb + 2;
            #pragma unroll
            for (int k = 0; k < 4; k++) {
                int idx = tid + k * 512;
                xr[k] = xb4[(size_t)(gbn + (idx >> 10)) * 1024 + (idx & 1023)];
            }
        }

        // ---- G0: L0 wmult  M=128 K=64 N=8 : X@W0 + b0 -> R2.B [h][s*8+c]
        for (int t = warp; t < 8; t += 16) {
            const int m0 = t * 16;
            float hh[4] = {0,0,0,0}, hl[4] = {0,0,0,0}, lh[4] = {0,0,0,0};
            tile3<false>(hh, hl, lh, sm + OR1H, sm + OR1L, 72, m0,
                         sm + OW0H, sm + OW0L, 72, 0, 0, 3, lane);
            float v[4];
            #pragma unroll
            for (int cr = 0; cr < 4; cr++)
                v[cr] = hh[cr] + hl[cr] + lh[cr] + sBias[ecol + (cr & 1)];
            int r0 = m0 + erow;
            int s = r0 >> 6;
            int o0 = (r0 & 63) * 72 + s * 8 + ecol;
            int o1 = ((r0 + 8) & 63) * 72 + s * 8 + ecol;
            bsplit2(sm + OR2 + o0, sm + OR2 + 4608 + o0, v[0], v[1]);
            bsplit2(sm + OR2 + o1, sm + OR2 + 4608 + o1, v[2], v[3]);
        }
        __syncthreads();

        // ---- G1: L0 mix  leaky(K0 @ R2) -> R3.B   M=64 N=16 (banded)
        for (int t = warp; t < 8; t += 16) {
            const int m0 = (t >> 1) * 16, n0 = (t & 1) * 8;
            int ktlo = max(0, m0 - R0) >> 4, kthi = min(63, m0 + 15 + R0) >> 4;
            float hh[4] = {0,0,0,0}, hl[4] = {0,0,0,0}, lh[4] = {0,0,0,0};
            tile3<true>(hh, hl, lh, sm + OKH, sm + OKL, 72, m0,
                        sm + OR2, sm + OR2 + 4608, 72, n0, ktlo, kthi, lane);
            float v[4];
            #pragma unroll
            for (int cr = 0; cr < 4; cr++) v[cr] = lrelu(hh[cr] + hl[cr] + lh[cr]);
            int r0 = m0 + erow, n = n0 + ecol;
            bsplit2(sm + OR3 + r0 * 72 + n, sm + OR3 + 4608 + r0 * 72 + n, v[0], v[1]);
            bsplit2(sm + OR3 + (r0 + 8) * 72 + n, sm + OR3 + 4608 + (r0 + 8) * 72 + n, v[2], v[3]);
        }
        __syncthreads();

        // ---- G2: L1 mix  K1 @ R3 -> R2.A [s*64+h][c] (+zero pad c8..15)
        for (int t = warp; t < 8; t += 16) {
            const int m0 = (t >> 1) * 16, n0 = (t & 1) * 8;
            int ktlo = max(0, m0 - R1b) >> 4, kthi = min(63, m0 + 15 + R1b) >> 4;
            float hh[4] = {0,0,0,0}, hl[4] = {0,0,0,0}, lh[4] = {0,0,0,0};
            tile3<true>(hh, hl, lh, sm + OKH + 4608, sm + OKL + 4608, 72, m0,
                        sm + OR3, sm + OR3 + 4608, 72, n0, ktlo, kthi, lane);
            float v[4];
            #pragma unroll
            for (int cr = 0; cr < 4; cr++) v[cr] = hh[cr] + hl[cr] + lh[cr];
            int n = n0 + ecol;
            int s = n >> 3, c = n & 7;
            int r0 = m0 + erow;
            int o0 = (s * 64 + r0) * 40 + c;
            int o1 = (s * 64 + r0 + 8) * 40 + c;
            bsplit2(sm + OR2 + o0, sm + OR2 + 5120 + o0, v[0], v[1]);
            bsplit2(sm + OR2 + o1, sm + OR2 + 5120 + o1, v[2], v[3]);
        }
        // zero k-pad cols 8..15 (stale data)
        if (tid < 256) {
            int row = tid >> 1, pl = tid & 1;
            uint4 z = make_uint4(0, 0, 0, 0);
            *(uint4*)(sm + OR2 + pl * 5120 + row * 40 + 8) = z;
        }
        __syncthreads();

        // ---- G3: L1 wmult  leaky(R2.A @ W1 + b1) -> R3.B  M=128 K=16 N=16
        for (int t = warp; t < 16; t += 16) {
            const int m0 = (t & 7) * 16, n0 = (t >> 3) * 8;
            float hh[4] = {0,0,0,0}, hl[4] = {0,0,0,0}, lh[4] = {0,0,0,0};
            tile3<false>(hh, hl, lh, sm + OR2, sm + OR2 + 5120, 40, m0,
                         sm + OW1H, sm + OW1L, 16, n0, 0, 0, lane);
            float v[4];
            #pragma unroll
            for (int cr = 0; cr < 4; cr++)
                v[cr] = lrelu(hh[cr] + hl[cr] + lh[cr] + sBias[8 + n0 + ecol + (cr & 1)]);
            int r0 = m0 + erow;
            int s = r0 >> 6;
            int col = n0 + ecol;
            int o0 = (r0 & 63) * 72 + s * 16 + col;
            int o1 = ((r0 + 8) & 63) * 72 + s * 16 + col;
            bsplit2(sm + OR3 + o0, sm + OR3 + 4608 + o0, v[0], v[1]);
            bsplit2(sm + OR3 + o1, sm + OR3 + 4608 + o1, v[2], v[3]);
        }
        __syncthreads();

        // ---- G4: L2 mix  K2 @ R3 -> R2.A  M=64 N=32 (banded)
        for (int t = warp; t < 16; t += 16) {
            const int m0 = (t & 3) * 16, n0 = (t >> 2) * 8;
            int ktlo = max(0, m0 - R2b) >> 4, kthi = min(63, m0 + 15 + R2b) >> 4;
            float hh[4] = {0,0,0,0}, hl[4] = {0,0,0,0}, lh[4] = {0,0,0,0};
            tile3<true>(hh, hl, lh, sm + OKH + 2 * 4608, sm + OKL + 2 * 4608, 72, m0,
                        sm + OR3, sm + OR3 + 4608, 72, n0, ktlo, kthi, lane);
            float v[4];
            #pragma unroll
            for (int cr = 0; cr < 4; cr++) v[cr] = hh[cr] + hl[cr] + lh[cr];
            int n = n0 + ecol;
            int s = n >> 4, c = n & 15;
            int r0 = m0 + erow;
            int o0 = (s * 64 + r0) * 40 + c;
            int o1 = (s * 64 + r0 + 8) * 40 + c;
            bsplit2(sm + OR2 + o0, sm + OR2 + 5120 + o0, v[0], v[1]);
            bsplit2(sm + OR2 + o1, sm + OR2 + 5120 + o1, v[2], v[3]);
        }
        __syncthreads();

        // ---- G5: L2 wmult  leaky(R2.A @ W2 + b2) -> R3.B  M=128 K=16 N=32
        for (int t = warp; t < 32; t += 16) {
            const int m0 = (t & 7) * 16, n0 = (t >> 3) * 8;
            float hh[4] = {0,0,0,0}, hl[4] = {0,0,0,0}, lh[4] = {0,0,0,0};
            tile3<false>(hh, hl, lh, sm + OR2, sm + OR2 + 5120, 40, m0,
                         sm + OW2H, sm + OW2L, 16, n0, 0, 0, lane);
            float v[4];
            #pragma unroll
            for (int cr = 0; cr < 4; cr++)
                v[cr] = lrelu(hh[cr] + hl[cr] + lh[cr] + sBias[24 + n0 + ecol + (cr & 1)]);
            int r0 = m0 + erow;
            int s = r0 >> 6;
            int col = n0 + ecol;
            int o0 = (r0 & 63) * 72 + s * 32 + col;
            int o1 = ((r0 + 8) & 63) * 72 + s * 32 + col;
            bsplit2(sm + OR3 + o0, sm + OR3 + 4608 + o0, v[0], v[1]);
            bsplit2(sm + OR3 + o1, sm + OR3 + 4608 + o1, v[2], v[3]);
        }
        __syncthreads();

        // ---- G6: L3 mix  K3 @ R3 -> R1.A [s*64+h][c] (stride 72)  M=64 N=64
        for (int t = warp; t < 32; t += 16) {
            const int m0 = (t & 3) * 16, n0 = (t >> 2) * 8;
            int ktlo = max(0, m0 - R3b) >> 4, kthi = min(63, m0 + 15 + R3b) >> 4;
            float hh[4] = {0,0,0,0}, hl[4] = {0,0,0,0}, lh[4] = {0,0,0,0};
            tile3<true>(hh, hl, lh, sm + OKH + 3 * 4608, sm + OKL + 3 * 4608, 72, m0,
                        sm + OR3, sm + OR3 + 4608, 72, n0, ktlo, kthi, lane);
            float v[4];
            #pragma unroll
            for (int cr = 0; cr < 4; cr++) v[cr] = hh[cr] + hl[cr] + lh[cr];
            int n = n0 + ecol;
            int s = n >> 5, c = n & 31;
            int r0 = m0 + erow;
            int o0 = (s * 64 + r0) * 72 + c;
            int o1 = (s * 64 + r0 + 8) * 72 + c;
            bsplit2(sm + OR1H + o0, sm + OR1L + o0, v[0], v[1]);
            bsplit2(sm + OR1H + o1, sm + OR1L + o1, v[2], v[3]);
        }
        __syncthreads();

        // ---- G7: L3 wmult  leaky(R1.A @ W3 + b3) -> hi plane R2, lo plane R3
        for (int t = warp; t < 64; t += 16) {
            const int m0 = (t & 7) * 16, n0 = (t >> 3) * 8;
            float hh[4] = {0,0,0,0}, hl[4] = {0,0,0,0}, lh[4] = {0,0,0,0};
            tile3<false>(hh, hl, lh, sm + OR1H, sm + OR1L, 72, m0,
                         sm + OW3H, sm + OW3L, 40, n0, 0, 1, lane);
            float v[4];
            #pragma unroll
            for (int cr = 0; cr < 4; cr++)
                v[cr] = lrelu(hh[cr] + hl[cr] + lh[cr] + sBias[56 + n0 + ecol + (cr & 1)]);
            int r0 = m0 + erow;
            int col = n0 + ecol;
            int o0 = r0 * 72 + col;
            int o1 = (r0 + 8) * 72 + col;
            bsplit2(sm + OR2 + o0, sm + OR3 + o0, v[0], v[1]);
            bsplit2(sm + OR2 + o1, sm + OR3 + o1, v[2], v[3]);
        }
        __syncthreads();

        // ---- copy out planes -> g_hHi/g_hLo [b][h*64+c] (16B stores) ----
        for (int idx = tid; idx < 1024; idx += 512) {
            int row = idx >> 3, ch = idx & 7;
            int s = row >> 6, h = row & 63;
            size_t go = (size_t)(gb + s) * 4096 + h * 64 + ch * 8;
            *(uint4*)(g_hHi + go) = *(const uint4*)(sm + OR2 + row * 72 + ch * 8);
            *(uint4*)(g_hLo + go) = *(const uint4*)(sm + OR3 + row * 72 + ch * 8);
        }
        __syncthreads();
    }
}

// ---------------------------------------------------------------------------
// Kernel C: tensor-core compress MLP (unchanged).
// ---------------------------------------------------------------------------
#define KC_STAGE_H   29952
#define KC_SA_H      0
#define KC_SA_L      9216
#define KC_SW_H      18432
#define KC_SW_L      24192
#define KC_F32_OFF   119808
#define KC_SMEM_BYTES (119808 + 21056)

__device__ __forceinline__ void kc_cpasync16(bf16* dst, const bf16* src) {
    unsigned d = (unsigned)__cvta_generic_to_shared(dst);
    asm volatile("cp.async.cg.shared.global [%0], [%1], 16;" :: "r"(d), "l"(src));
}

__global__ __launch_bounds__(256) void kernC(const float* __restrict__ bm0,
                                             const float* __restrict__ wm1,
                                             const float* __restrict__ bm1,
                                             float* __restrict__ out)
{
    extern __shared__ __align__(16) char smc[];
    bf16* sh = (bf16*)smc;
    float* fpers = (float*)(smc + KC_F32_OFF);
    float* sWm1t = fpers;            // [80][64]
    float* sBm0  = fpers + 5120;
    float* sBm1  = fpers + 5200;
    float* sOut1 = (float*)smc;      // [128][84] after k-loop

    const int tid  = threadIdx.x;
    const int lane = tid & 31;
    const int warp = tid >> 5;
    const int wm = warp >> 1, wn = warp & 1;
    const int m0 = blockIdx.x * 128;

    for (int idx = tid; idx < 4800; idx += 256) {
        int o = idx / 80, c = idx % 80;
        sWm1t[c * 64 + o] = wm1[idx];
    }
    if (tid < 80) sBm0[tid] = bm0[tid];
    if (tid < 60) sBm1[tid] = bm1[tid];

    auto load_stage = [&](int kb, int st) {
        bf16* base = sh + st * KC_STAGE_H;
        const size_t kcol = (size_t)kb * 64;
        #pragma unroll
        for (int c = tid; c < 1024; c += 256) {
            int r = c >> 3, o = c & 7;
            kc_cpasync16(base + KC_SA_H + r * 72 + o * 8,
                         g_hHi + (size_t)(m0 + r) * 4096 + kcol + o * 8);
        }
        #pragma unroll
        for (int c = tid; c < 1024; c += 256) {
            int r = c >> 3, o = c & 7;
            kc_cpasync16(base + KC_SA_L + r * 72 + o * 8,
                         g_hLo + (size_t)(m0 + r) * 4096 + kcol + o * 8);
        }
        for (int c = tid; c < 640; c += 256) {
            int r = c >> 3, o = c & 7;
            kc_cpasync16(base + KC_SW_H + r * 72 + o * 8,
                         g_wHi + (size_t)r * 4096 + kcol + o * 8);
        }
        for (int c = tid; c < 640; c += 256) {
            int r = c >> 3, o = c & 7;
            kc_cpasync16(base + KC_SW_L + r * 72 + o * 8,
                         g_wLo + (size_t)r * 4096 + kcol + o * 8);
        }
    };

    float acc[2][5][4];
    #pragma unroll
    for (int i = 0; i < 2; i++)
        #pragma unroll
        for (int j = 0; j < 5; j++)
            #pragma unroll
            for (int k = 0; k < 4; k++) acc[i][j][k] = 0.f;

    load_stage(0, 0);
    asm volatile("cp.async.commit_group;");

    const int aq  = lane >> 3;
    const int arn = lane & 7;
    const int a_row_off = (aq & 1) * 8 + arn;
    const int a_col_off = (aq >> 1) * 8;
    const int bl  = lane & 15;
    const int b_rn = bl & 7;
    const int b_hi8 = (bl >> 3) * 8;

    const int NK = 64;
    for (int kb = 0; kb < NK; kb++) {
        if (kb + 1 < NK) {
            load_stage(kb + 1, (kb + 1) & 1);
            asm volatile("cp.async.commit_group;");
            asm volatile("cp.async.wait_group 1;");
        } else {
            asm volatile("cp.async.wait_group 0;");
        }
        __syncthreads();

        bf16* base = sh + (kb & 1) * KC_STAGE_H;
        bf16* sAh = base + KC_SA_H;
        bf16* sAl = base + KC_SA_L;
        bf16* sWh = base + KC_SW_H;
        bf16* sWl = base + KC_SW_L;

        #pragma unroll
        for (int sub = 0; sub < 4; sub++) {
            const int kc = sub * 16;
            unsigned bh[5][2], blo[5][2];
            #pragma unroll
            for (int n = 0; n < 5; n++) {
                const int brow = wn * 40 + n * 8 + b_rn;
                ldx2(bh[n],  sWh + brow * 72 + kc + b_hi8);
                ldx2(blo[n], sWl + brow * 72 + kc + b_hi8);
            }
            #pragma unroll
            for (int tmt = 0; tmt < 2; tmt++) {
                const int arow = wm * 32 + tmt * 16 + a_row_off;
                unsigned ah[4], al[4];
                ldx4(ah, sAh + arow * 72 + kc + a_col_off);
                ldx4(al, sAl + arow * 72 + kc + a_col_off);
                #pragma unroll
                for (int n = 0; n < 5; n++) {
                    hmma(acc[tmt][n], ah, bh[n]);
                    hmma(acc[tmt][n], ah, blo[n]);
                    hmma(acc[tmt][n], al, bh[n]);
                }
            }
        }
        __syncthreads();
    }

    #pragma unroll
    for (int tmt = 0; tmt < 2; tmt++)
        #pragma unroll
        for (int n = 0; n < 5; n++)
            #pragma unroll
            for (int cr = 0; cr < 4; cr++) {
                int row = wm * 32 + tmt * 16 + (lane >> 2) + ((cr >= 2) ? 8 : 0);
                int col = wn * 40 + n * 8 + (lane & 3) * 2 + (cr & 1);
                float v = acc[tmt][n][cr] + sBm0[col];
                v = v > 0.f ? v : v * NEG;
                sOut1[row * 84 + col] = v;
            }
    __syncthreads();

    {
        const int tr = tid >> 4;
        const int tc = tid & 15;
        float a2[8][4];
        #pragma unroll
        for (int i = 0; i < 8; i++)
            #pragma unroll
            for (int j = 0; j < 4; j++) a2[i][j] = 0.f;
        for (int c = 0; c < 80; c++) {
            float wv[4];
            #pragma unroll
            for (int j = 0; j < 4; j++) {
                int o = tc * 4 + j;
                wv[j] = (o < 60) ? sWm1t[c * 64 + o] : 0.f;
            }
            #pragma unroll
            for (int i = 0; i < 8; i++) {
                float cv = sOut1[(tr + 16 * i) * 84 + c];
                #pragma unroll
                for (int j = 0; j < 4; j++)
                    a2[i][j] = fmaf(cv, wv[j], a2[i][j]);
            }
        }
        #pragma unroll
        for (int i = 0; i < 8; i++)
            #pragma unroll
            for (int j = 0; j < 4; j++) {
                int o = tc * 4 + j;
                if (o < 60) {
                    float v = a2[i][j] + sBm1[o];
                    v = v > 0.f ? v : v * NEG;
                    out[(size_t)(m0 + tr + 16 * i) * 60 + o] = v;
                }
            }
    }
}

// ---------------------------------------------------------------------------
extern "C" void kernel_launch(void* const* d_in, const int* in_sizes, int n_in,
                              void* d_out, int out_size) {
    (void)in_sizes; (void)n_in; (void)out_size;
    const float* x   = (const float*)d_in[0];
    const float* w0  = (const float*)d_in[1];
    const float* b0  = (const float*)d_in[2];
    const float* s0  = (const float*)d_in[3];
    const float* w1  = (const float*)d_in[4];
    const float* b1  = (const float*)d_in[5];
    const float* s1  = (const float*)d_in[6];
    const float* w2  = (const float*)d_in[7];
    const float* b2  = (const float*)d_in[8];
    const float* s2  = (const float*)d_in[9];
    const float* w3  = (const float*)d_in[10];
    const float* b3  = (const float*)d_in[11];
    const float* s3  = (const float*)d_in[12];
    const float* wm0 = (const float*)d_in[13];
    const float* bm0 = (const float*)d_in[14];
    const float* wm1 = (const float*)d_in[15];
    const float* bm1 = (const float*)d_in[16];
    float* out = (float*)d_out;

    static int attr_done = 0;
    if (!attr_done) {
        cudaFuncSetAttribute(kernG, cudaFuncAttributeMaxDynamicSharedMemorySize, KG_SMEM_BYTES);
        cudaFuncSetAttribute(kernC, cudaFuncAttributeMaxDynamicSharedMemorySize, KC_SMEM_BYTES);
        attr_done = 1;
    }

    kernK<<<1, 256>>>(s0, s1, s2, s3);
    kernT<<<1280, 256>>>(wm0);
    kernG<<<1024, 512, KG_SMEM_BYTES>>>(x, w0, b0, w1, b1, w2, b2, w3, b3);
    kernC<<<128, 256, KC_SMEM_BYTES>>>(bm0, wm1, bm1, out);
}